// round 7
// baseline (speedup 1.0000x reference)
#include <cuda_runtime.h>
#include <stdint.h>

#define NHEAD 8
#define DMODEL 512
#define MAXELEMS (4*2048*512)

// Scratch (allocation-free rule: __device__ globals)
__device__ float g_qp[MAXELEMS];
__device__ float g_kp[MAXELEMS];
__device__ float g_vp[MAXELEMS];
__device__ float g_ctx[MAXELEMS];

// ---------------------------------------------------------------------------
// tf32 helpers + warp mma (legacy path: valid on plain sm_103 target)
// ---------------------------------------------------------------------------
__device__ __forceinline__ unsigned f2tf(float x) {
    unsigned r;
    asm("cvt.rna.tf32.f32 %0, %1;" : "=r"(r) : "f"(x));
    return r;
}
__device__ __forceinline__ float ftf(float x) { return __uint_as_float(f2tf(x)); }

__device__ __forceinline__ void mma8(float c[4], const unsigned a[4], const unsigned b[2]) {
    asm volatile("mma.sync.aligned.m16n8k8.row.col.f32.tf32.tf32.f32 "
                 "{%0,%1,%2,%3}, {%4,%5,%6,%7}, {%8,%9}, {%0,%1,%2,%3};"
                 : "+f"(c[0]), "+f"(c[1]), "+f"(c[2]), "+f"(c[3])
                 : "r"(a[0]), "r"(a[1]), "r"(a[2]), "r"(a[3]), "r"(b[0]), "r"(b[1]));
}

// cp.async (LDGSTS) helpers
__device__ __forceinline__ void cp16(unsigned dst, const void* src) {
    asm volatile("cp.async.cg.shared.global [%0], [%1], 16;" :: "r"(dst), "l"(src));
}
#define CP_COMMIT() asm volatile("cp.async.commit_group;" ::: "memory")
#define CP_WAIT1()  asm volatile("cp.async.wait_group 1;" ::: "memory")

// fast exp on FMA pipe (rel err ~1e-7)
__device__ __forceinline__ float fexp(float x) {
    float t = fmaf(x, 1.4426950408889634f, 12582912.0f);
    int ni = __float_as_int(t) - 0x4B400000;
    float n = t - 12582912.0f;
    float r = fmaf(n, -0.693145751953125f, x);
    r = fmaf(n, -1.428606765330187e-06f, r);
    float q = 1.3888889e-3f;
    q = fmaf(q, r, 8.3333333e-3f);
    q = fmaf(q, r, 4.1666667e-2f);
    q = fmaf(q, r, 1.6666667e-1f);
    q = fmaf(q, r, 0.5f);
    q = fmaf(q, r, 1.0f);
    q = fmaf(q, r, 1.0f);
    return q * __int_as_float(0x3F800000 + (ni << 23));
}

// ---------------------------------------------------------------------------
// Kernel 1: projections as GEMM (unchanged; 28us, memory/latency-bound).
// ---------------------------------------------------------------------------
__global__ __launch_bounds__(256) void proj_tc(
    const float* __restrict__ q, const float* __restrict__ k, const float* __restrict__ v,
    const float* __restrict__ Wq, const float* __restrict__ Wk, const float* __restrict__ Wv,
    const float* __restrict__ bq, const float* __restrict__ bk, const float* __restrict__ bv)
{
    extern __shared__ float sm[];
    float* As = sm;             // [128][72]
    float* Ws = sm + 128 * 72;  // [64][72]

    const int tid = threadIdx.x, w = tid >> 5, lid = tid & 31;
    const int g = lid >> 2, t4 = lid & 3;
    const int which = blockIdx.y;
    const float* x  = which == 0 ? q  : which == 1 ? k  : v;
    const float* W  = which == 0 ? Wq : which == 1 ? Wk : Wv;
    const float* bb = which == 0 ? bq : which == 1 ? bk : bv;
    float* dst = which == 0 ? g_qp : which == 1 ? g_kp : g_vp;
    const long r0 = (long)blockIdx.x * 128;

#pragma unroll
    for (int i = 0; i < 8; ++i) {
        int f = tid + i * 256, r = f >> 4, e4 = f & 15;
        float4 a = *(const float4*)(x + (r0 + r) * 64 + e4 * 4);
        a.x = ftf(a.x); a.y = ftf(a.y); a.z = ftf(a.z); a.w = ftf(a.w);
        *(float4*)&As[r * 72 + e4 * 4] = a;
    }
#pragma unroll
    for (int i = 0; i < 4; ++i) {
        int f = tid + i * 256, r = f >> 4, e4 = f & 15;
        float4 a = *(const float4*)(W + r * 64 + e4 * 4);
        a.x = ftf(a.x); a.y = ftf(a.y); a.z = ftf(a.z); a.w = ftf(a.w);
        *(float4*)&Ws[r * 72 + e4 * 4] = a;
    }
    __syncthreads();

    const unsigned* Au = (const unsigned*)As;
    const unsigned* Wu = (const unsigned*)Ws;
    float acc[8][4] = {};
#pragma unroll
    for (int ks = 0; ks < 8; ++ks) {
        unsigned a[4];
        int ar = (16 * w + g) * 72 + ks * 8 + t4;
        a[0] = Au[ar]; a[1] = Au[ar + 8 * 72]; a[2] = Au[ar + 4]; a[3] = Au[ar + 8 * 72 + 4];
#pragma unroll
        for (int nb = 0; nb < 8; ++nb) {
            unsigned bf[2];
            int br = (ks * 8 + t4) * 72 + nb * 8 + g;
            bf[0] = Wu[br]; bf[1] = Wu[br + 4 * 72];
            mma8(acc[nb], a, bf);
        }
    }

    const long row0 = (r0 + 16 * w + g) * 64;
    const long row1 = row0 + 8 * 64;
#pragma unroll
    for (int nb = 0; nb < 8; ++nb) {
        int c = nb * 8 + 2 * t4;
        float b0v = bb[c], b1v = bb[c + 1];
        *(float2*)(dst + row0 + c) = make_float2(acc[nb][0] + b0v, acc[nb][1] + b1v);
        *(float2*)(dst + row1 + c) = make_float2(acc[nb][2] + b0v, acc[nb][3] + b1v);
    }
}

// ---------------------------------------------------------------------------
// Kernel 2: key-split tf32 flash attention.
// CTA = 128 q x (b,h); 8 warps = 4 q-groups(32 q) x 2 key-halves(32 keys).
// Q in registers (A of S=Q@K^T); P transposed c-frag -> a-frag via shfl
// (no Pt smem, no intra-tile CTA syncs); partial ctx/l combined at epilogue.
// Pane strides: K/Q 76 (12 mod 32), V 72 (8 mod 32) -> all frag LDS
// conflict-free. Double-buffered K/V via cp.async.
// ---------------------------------------------------------------------------
#define QSTR 76
#define KSTR 76
#define VSTR 72
#define SM_Q  0                         // 128*76 = 9728 floats (reused as C pane)
#define SM_K  9728                      // 2 stages x 64*76
#define SM_V  (SM_K + 2*64*KSTR)        // 2 stages x 64*72
#define SM_LR (SM_V + 2*64*VSTR)        // 256 floats
#define SM_ATTN_FLOATS (SM_LR + 256)    // 28928 floats = 115712 B

__device__ __forceinline__ void issue_tile(float* pane, int stride,
                                           const float* gsrc, int tid) {
    unsigned base = (unsigned)__cvta_generic_to_shared(pane);
#pragma unroll
    for (int i = 0; i < 4; ++i) {
        int f = tid + i * 256, r = f >> 4, e4 = f & 15;
        cp16(base + (unsigned)(r * stride + e4 * 4) * 4u,
             gsrc + (long)r * DMODEL + e4 * 4);
    }
}

__global__ __launch_bounds__(256, 1) void attn_mma(const int* __restrict__ valid_lens, int S)
{
    extern __shared__ float sm[];
    float* Qp  = sm + SM_Q;
    float* lred = sm + SM_LR;

    const int tid = threadIdx.x, w = tid >> 5, lid = tid & 31;
    const int gid = lid >> 2, t4 = lid & 3;
    const int qg = w >> 1;            // q-group (32 q rows)
    const int half = w & 1;           // key half (32 keys)
    const int key0 = half * 32;

    const int h = blockIdx.y, b = blockIdx.z;
    const int s0 = blockIdx.x * 128;
    const int valid = valid_lens[b];
    const long gbase = (long)b * S * DMODEL + h * 64;
    const float* kg = g_kp + gbase;
    const float* vg = g_vp + gbase;

    const int nt = (valid + 63) >> 6;

    // ---- prefetch tiles 0 and 1 (K+V each) ----
    issue_tile(sm + SM_K, KSTR, kg, tid);
    issue_tile(sm + SM_V, VSTR, vg, tid);
    CP_COMMIT();
    if (nt > 1) {
        issue_tile(sm + SM_K + 64 * KSTR, KSTR, kg + 64 * DMODEL, tid);
        issue_tile(sm + SM_V + 64 * VSTR, VSTR, vg + 64 * DMODEL, tid);
    }
    CP_COMMIT();

    // ---- stage Q [128 x 64] (scaled, RNA tf32), extract a-frags to regs ----
#pragma unroll
    for (int i = 0; i < 8; ++i) {
        int f = tid + i * 256, r = f >> 4, e4 = f & 15;
        float4 a = *(const float4*)(g_qp + gbase + (long)(s0 + r) * DMODEL + e4 * 4);
        a.x = ftf(a.x * 0.125f); a.y = ftf(a.y * 0.125f);
        a.z = ftf(a.z * 0.125f); a.w = ftf(a.w * 0.125f);
        *(float4*)&Qp[r * QSTR + e4 * 4] = a;
    }
    __syncthreads();
    unsigned Qf[2][8][4];
    {
        const unsigned* Qu = (const unsigned*)Qp;
#pragma unroll
        for (int mb = 0; mb < 2; ++mb)
#pragma unroll
            for (int ks = 0; ks < 8; ++ks) {
                int qa = (qg * 32 + mb * 16 + gid) * QSTR + ks * 8 + t4;
                Qf[mb][ks][0] = Qu[qa];
                Qf[mb][ks][1] = Qu[qa + 8 * QSTR];
                Qf[mb][ks][2] = Qu[qa + 4];
                Qf[mb][ks][3] = Qu[qa + 8 * QSTR + 4];
            }
    }
    CP_WAIT1();
    __syncthreads();   // tile 0 visible; Q pane reads done

    float octx[2][8][4] = {};
    float lsum[2][2] = {{0.f, 0.f}, {0.f, 0.f}};
    const int s0lane = (lid & 28) | (t4 >> 1);
    const int s1lane = s0lane + 2;
    const bool oddt = (t4 & 1);

    for (int t = 0; t < nt; ++t) {
        const unsigned* Ku = (const unsigned*)(sm + SM_K + (t & 1) * 64 * KSTR);
        const unsigned* Vu = (const unsigned*)(sm + SM_V + (t & 1) * 64 * VSTR);
        const int j0 = t * 64;

        // ---- S = Q @ K^T : m=32 q (2 mb), n=32 keys (4 nb), k=64 (8 ks) ----
        float sacc[2][4][4] = {};
#pragma unroll
        for (int ks = 0; ks < 8; ++ks) {
            unsigned bf[4][2];
#pragma unroll
            for (int nb = 0; nb < 4; ++nb) {
                int br = (key0 + nb * 8 + gid) * KSTR + ks * 8 + t4;
                bf[nb][0] = Ku[br];
                bf[nb][1] = Ku[br + 4];
            }
#pragma unroll
            for (int mb = 0; mb < 2; ++mb)
#pragma unroll
                for (int nb = 0; nb < 4; ++nb)
                    mma8(sacc[mb][nb], Qf[mb][ks], bf[nb]);
        }

        // ---- exp + mask + lsum + shfl-transpose to PV a-frags ----
        unsigned pa[2][4][4];
#pragma unroll
        for (int mb = 0; mb < 2; ++mb)
#pragma unroll
            for (int nb = 0; nb < 4; ++nb) {
                const int kk = j0 + key0 + nb * 8;
                const int ka = kk + 2 * t4, kb2 = ka + 1;
                float e0 = ka  < valid ? fexp(sacc[mb][nb][0]) : 0.f;
                float e1 = kb2 < valid ? fexp(sacc[mb][nb][1]) : 0.f;
                float e2 = ka  < valid ? fexp(sacc[mb][nb][2]) : 0.f;
                float e3 = kb2 < valid ? fexp(sacc[mb][nb][3]) : 0.f;
                lsum[mb][0] += e0 + e1;
                lsum[mb][1] += e2 + e3;
                float u0 = __shfl_sync(0xffffffffu, e0, s0lane);
                float u1 = __shfl_sync(0xffffffffu, e1, s0lane);
                float v0 = __shfl_sync(0xffffffffu, e0, s1lane);
                float v1 = __shfl_sync(0xffffffffu, e1, s1lane);
                float w0 = __shfl_sync(0xffffffffu, e2, s0lane);
                float w1 = __shfl_sync(0xffffffffu, e3, s0lane);
                float x0 = __shfl_sync(0xffffffffu, e2, s1lane);
                float x1 = __shfl_sync(0xffffffffu, e3, s1lane);
                pa[mb][nb][0] = f2tf(oddt ? u1 : u0);
                pa[mb][nb][1] = f2tf(oddt ? w1 : w0);
                pa[mb][nb][2] = f2tf(oddt ? v1 : v0);
                pa[mb][nb][3] = f2tf(oddt ? x1 : x0);
            }

        // ---- ctx += P @ V : m=32 q, n=64 e (8 nb), k=32 keys (4 kb) ----
#pragma unroll
        for (int kb = 0; kb < 4; ++kb) {
            unsigned vb[8][2];
#pragma unroll
            for (int nb = 0; nb < 8; ++nb) {
                int br = (key0 + kb * 8 + t4) * VSTR + nb * 8 + gid;
                vb[nb][0] = Vu[br];
                vb[nb][1] = Vu[br + 4 * VSTR];
            }
#pragma unroll
            for (int mb = 0; mb < 2; ++mb)
#pragma unroll
                for (int nb = 0; nb < 8; ++nb)
                    mma8(octx[mb][nb], pa[mb][kb], vb[nb]);
        }

        __syncthreads();   // all warps done reading stage t&1
        if (t + 2 < nt) {
            issue_tile(sm + SM_K + (t & 1) * 64 * KSTR, KSTR, kg + (long)(t + 2) * 64 * DMODEL, tid);
            issue_tile(sm + SM_V + (t & 1) * 64 * VSTR, VSTR, vg + (long)(t + 2) * 64 * DMODEL, tid);
        }
        CP_COMMIT();
        CP_WAIT1();        // tile t+1 done
        __syncthreads();
    }

    // ---- epilogue: combine key-halves ----
    // 1) softmax denominators: reduce over t4 lanes, publish per half.
#pragma unroll
    for (int mb = 0; mb < 2; ++mb)
#pragma unroll
        for (int r = 0; r < 2; ++r) {
            float vv = lsum[mb][r];
            vv += __shfl_xor_sync(0xffffffffu, vv, 1);
            vv += __shfl_xor_sync(0xffffffffu, vv, 2);
            if (t4 == 0) lred[half * 128 + qg * 32 + mb * 16 + r * 8 + gid] = vv;
        }
    __syncthreads();

    // 2) half 0 stores partial ctx into the (dead) Q pane.
    if (half == 0) {
#pragma unroll
        for (int mb = 0; mb < 2; ++mb) {
            float* r0p = Qp + (qg * 32 + mb * 16 + gid) * QSTR;
            float* r1p = r0p + 8 * QSTR;
#pragma unroll
            for (int nb = 0; nb < 8; ++nb) {
                int c = nb * 8 + 2 * t4;
                *(float2*)(r0p + c) = make_float2(octx[mb][nb][0], octx[mb][nb][1]);
                *(float2*)(r1p + c) = make_float2(octx[mb][nb][2], octx[mb][nb][3]);
            }
        }
    }
    __syncthreads();

    // 3) half 1 adds its partial, normalizes, stores to gmem.
    if (half == 1) {
#pragma unroll
        for (int mb = 0; mb < 2; ++mb) {
            const int qr = qg * 32 + mb * 16 + gid;
            const float inv0 = 1.0f / (lred[qr] + lred[128 + qr]);
            const float inv1 = 1.0f / (lred[qr + 8] + lred[128 + qr + 8]);
            const float* r0p = Qp + qr * QSTR;
            const float* r1p = r0p + 8 * QSTR;
            float* o0 = g_ctx + gbase + (long)(s0 + qr) * DMODEL;
            float* o1 = o0 + 8 * DMODEL;
#pragma unroll
            for (int nb = 0; nb < 8; ++nb) {
                int c = nb * 8 + 2 * t4;
                float2 p0 = *(const float2*)(r0p + c);
                float2 p1 = *(const float2*)(r1p + c);
                *(float2*)(o0 + c) = make_float2((p0.x + octx[mb][nb][0]) * inv0,
                                                 (p0.y + octx[mb][nb][1]) * inv0);
                *(float2*)(o1 + c) = make_float2((p1.x + octx[mb][nb][2]) * inv1,
                                                 (p1.y + octx[mb][nb][3]) * inv1);
            }
        }
    }
}

// ---------------------------------------------------------------------------
// Kernel 3: output projection out = ctx @ Wo + bo  (tf32 mma, unchanged).
// ---------------------------------------------------------------------------
__global__ __launch_bounds__(256) void outp_tc(
    const float* __restrict__ Wo, const float* __restrict__ bo, float* __restrict__ out)
{
    extern __shared__ float sm[];
    float* As = sm;             // [128][72]
    float* Ws = sm + 128 * 72;  // [64][72]

    const int tid = threadIdx.x, w = tid >> 5, lid = tid & 31;
    const int g = lid >> 2, t4 = lid & 3;
    const long r0 = (long)blockIdx.y * 128;
    const int n0 = blockIdx.x * 64;

    float acc[8][4] = {};
    for (int k0 = 0; k0 < DMODEL; k0 += 64) {
        if (k0) __syncthreads();
#pragma unroll
        for (int i = 0; i < 8; ++i) {
            int f = tid + i * 256, r = f >> 4, e4 = f & 15;
            float4 a = *(const float4*)(g_ctx + (r0 + r) * DMODEL + k0 + e4 * 4);
            a.x = ftf(a.x); a.y = ftf(a.y); a.z = ftf(a.z); a.w = ftf(a.w);
            *(float4*)&As[r * 72 + e4 * 4] = a;
        }
#pragma unroll
        for (int i = 0; i < 4; ++i) {
            int f = tid + i * 256, r = f >> 4, e4 = f & 15;
            float4 a = *(const float4*)(Wo + (long)(k0 + r) * DMODEL + n0 + e4 * 4);
            a.x = ftf(a.x); a.y = ftf(a.y); a.z = ftf(a.z); a.w = ftf(a.w);
            *(float4*)&Ws[r * 72 + e4 * 4] = a;
        }
        __syncthreads();

        const unsigned* Au = (const unsigned*)As;
        const unsigned* Wu = (const unsigned*)Ws;
#pragma unroll
        for (int ks = 0; ks < 8; ++ks) {
            unsigned a[4];
            int ar = (16 * w + g) * 72 + ks * 8 + t4;
            a[0] = Au[ar]; a[1] = Au[ar + 8 * 72];
            a[2] = Au[ar + 4]; a[3] = Au[ar + 8 * 72 + 4];
#pragma unroll
            for (int nb = 0; nb < 8; ++nb) {
                unsigned bf[2];
                int br = (ks * 8 + t4) * 72 + nb * 8 + g;
                bf[0] = Wu[br]; bf[1] = Wu[br + 4 * 72];
                mma8(acc[nb], a, bf);
            }
        }
    }

    const long row0 = (r0 + 16 * w + g) * DMODEL + n0;
    const long row1 = row0 + 8 * DMODEL;
#pragma unroll
    for (int nb = 0; nb < 8; ++nb) {
        int c = nb * 8 + 2 * t4;
        float b0v = bo[n0 + c], b1v = bo[n0 + c + 1];
        *(float2*)(out + row0 + c) = make_float2(acc[nb][0] + b0v, acc[nb][1] + b1v);
        *(float2*)(out + row1 + c) = make_float2(acc[nb][2] + b0v, acc[nb][3] + b1v);
    }
}

// ---------------------------------------------------------------------------
// launch
// inputs: 0:q 1:k 2:v 3:Wq 4:bq 5:Wk 6:bk 7:Wv 8:bv 9:Wo 10:bo 11:valid_lens 12:max_len
// ---------------------------------------------------------------------------
extern "C" void kernel_launch(void* const* d_in, const int* in_sizes, int n_in,
                              void* d_out, int out_size)
{
    const float* q  = (const float*)d_in[0];
    const float* k  = (const float*)d_in[1];
    const float* v  = (const float*)d_in[2];
    const float* Wq = (const float*)d_in[3];
    const float* bq = (const float*)d_in[4];
    const float* Wk = (const float*)d_in[5];
    const float* bk = (const float*)d_in[6];
    const float* Wv = (const float*)d_in[7];
    const float* bv = (const float*)d_in[8];
    const float* Wo = (const float*)d_in[9];
    const float* bo = (const float*)d_in[10];
    const int* valid_lens = (const int*)d_in[11];
    float* out = (float*)d_out;

    const int B = in_sizes[11];
    const int S = in_sizes[0] / (B * DMODEL);
    const int BS = B * S;

    const int smGemm = (128 * 72 + 64 * 72) * (int)sizeof(float);   // 55296 B
    const int smAttn = SM_ATTN_FLOATS * (int)sizeof(float);         // 115712 B

    // 1) projections (x viewed as [BS*8, 64] rows)
    cudaFuncSetAttribute(proj_tc, cudaFuncAttributeMaxDynamicSharedMemorySize, smGemm);
    proj_tc<<<dim3(BS * 8 / 128, 3), 256, smGemm>>>(q, k, v, Wq, Wk, Wv, bq, bk, bv);

    // 2) attention (key-split warps, register P, double-buffered K/V)
    cudaFuncSetAttribute(attn_mma, cudaFuncAttributeMaxDynamicSharedMemorySize, smAttn);
    attn_mma<<<dim3(S / 128, NHEAD, B), 256, smAttn>>>(valid_lens, S);

    // 3) output projection
    cudaFuncSetAttribute(outp_tc, cudaFuncAttributeMaxDynamicSharedMemorySize, smGemm);
    outp_tc<<<dim3(DMODEL / 64, BS / 128), 256, smGemm>>>(Wo, bo, out);
}

// round 8
// speedup vs baseline: 1.7427x; 1.7427x over previous
#include <cuda_runtime.h>
#include <cuda_fp16.h>
#include <stdint.h>

#define NHEAD 8
#define DMODEL 512
#define MAXELEMS (4*2048*512)

// Scratch (allocation-free rule: __device__ globals) — fp16 activations
__device__ __half g_qph[MAXELEMS];   // pre-scaled by 1/8
__device__ __half g_kph[MAXELEMS];
__device__ __half g_vph[MAXELEMS];
__device__ __half g_ctxh[MAXELEMS];

// ---------------------------------------------------------------------------
// fp16 mma + ldmatrix helpers (legacy path: valid on plain sm_103 target)
// ---------------------------------------------------------------------------
__device__ __forceinline__ void mma16(float c[4], const unsigned a[4],
                                      unsigned b0, unsigned b1) {
    asm volatile("mma.sync.aligned.m16n8k16.row.col.f32.f16.f16.f32 "
                 "{%0,%1,%2,%3}, {%4,%5,%6,%7}, {%8,%9}, {%0,%1,%2,%3};"
                 : "+f"(c[0]), "+f"(c[1]), "+f"(c[2]), "+f"(c[3])
                 : "r"(a[0]), "r"(a[1]), "r"(a[2]), "r"(a[3]), "r"(b0), "r"(b1));
}
__device__ __forceinline__ void ldmat4t(unsigned& r0, unsigned& r1,
                                        unsigned& r2, unsigned& r3, unsigned addr) {
    asm volatile("ldmatrix.sync.aligned.m8n8.x4.trans.shared.b16 {%0,%1,%2,%3}, [%4];"
                 : "=r"(r0), "=r"(r1), "=r"(r2), "=r"(r3) : "r"(addr));
}
__device__ __forceinline__ unsigned pkh2(float a, float b) {
    __half2 h = __floats2half2_rn(a, b);
    return *reinterpret_cast<unsigned*>(&h);
}

// cp.async helpers
__device__ __forceinline__ void cp16(unsigned dst, const void* src) {
    asm volatile("cp.async.cg.shared.global [%0], [%1], 16;" :: "r"(dst), "l"(src));
}
#define CP_COMMIT() asm volatile("cp.async.commit_group;" ::: "memory")
#define CP_WAIT(n)  asm volatile("cp.async.wait_group %0;" :: "n"(n) : "memory")

// fast exp on FMA pipe (rel err ~1e-7)
__device__ __forceinline__ float fexp(float x) {
    float t = fmaf(x, 1.4426950408889634f, 12582912.0f);
    int ni = __float_as_int(t) - 0x4B400000;
    float n = t - 12582912.0f;
    float r = fmaf(n, -0.693145751953125f, x);
    r = fmaf(n, -1.428606765330187e-06f, r);
    float q = 1.3888889e-3f;
    q = fmaf(q, r, 8.3333333e-3f);
    q = fmaf(q, r, 4.1666667e-2f);
    q = fmaf(q, r, 1.6666667e-1f);
    q = fmaf(q, r, 0.5f);
    q = fmaf(q, r, 1.0f);
    q = fmaf(q, r, 1.0f);
    return q * __int_as_float(0x3F800000 + (ni << 23));
}

// pane row stride: 72 halfs (= 36 half2; 36 mod 32 = 4 -> conflict-free frags;
// 144 B row stride = 9 x 16B -> ldmatrix-aligned, conflict-free phases)
#define PSTR 72
#define PSTR2 36

// ---------------------------------------------------------------------------
// Kernel 1: projections (x viewed as [BS*8, 64] rows; W shared across heads).
// fp16 m16n8k16: warp = 16 rows x 64 cols, K=64 -> 4 kb x 8 nb = 32 mma.
// B-frags (W k-major pairs) via ldmatrix.trans. q output pre-scaled by 1/8.
// ---------------------------------------------------------------------------
__global__ __launch_bounds__(256) void proj_tc(
    const float* __restrict__ q, const float* __restrict__ k, const float* __restrict__ v,
    const float* __restrict__ Wq, const float* __restrict__ Wk, const float* __restrict__ Wv,
    const float* __restrict__ bq, const float* __restrict__ bk, const float* __restrict__ bv)
{
    extern __shared__ char smc[];
    __half* As = (__half*)smc;                // [128][72]
    __half* Ws = (__half*)smc + 128 * PSTR;   // [64][72]

    const int tid = threadIdx.x, w = tid >> 5, lid = tid & 31;
    const int g = lid >> 2, t4 = lid & 3;
    const int which = blockIdx.y;
    const float* x  = which == 0 ? q  : which == 1 ? k  : v;
    const float* W  = which == 0 ? Wq : which == 1 ? Wk : Wv;
    const float* bb = which == 0 ? bq : which == 1 ? bk : bv;
    __half* dst = which == 0 ? g_qph : which == 1 ? g_kph : g_vph;
    const float scale = which == 0 ? 0.125f : 1.0f;
    const long r0 = (long)blockIdx.x * 128;

    // stage x (cvt fp32->fp16): 128 rows x 16 float4 chunks
#pragma unroll
    for (int i = 0; i < 8; ++i) {
        int f = tid + i * 256, r = f >> 4, c = f & 15;
        float4 a = *(const float4*)(x + (r0 + r) * 64 + c * 4);
        *(uint2*)&As[r * PSTR + c * 4] = make_uint2(pkh2(a.x, a.y), pkh2(a.z, a.w));
    }
    // stage W
#pragma unroll
    for (int i = 0; i < 4; ++i) {
        int f = tid + i * 256, r = f >> 4, c = f & 15;
        float4 a = *(const float4*)(W + r * 64 + c * 4);
        *(uint2*)&Ws[r * PSTR + c * 4] = make_uint2(pkh2(a.x, a.y), pkh2(a.z, a.w));
    }
    __syncthreads();

    const unsigned* Au = (const unsigned*)As;
    unsigned af[4][4];
#pragma unroll
    for (int kb = 0; kb < 4; ++kb) {
        int ar = (16 * w + g) * PSTR2 + kb * 8 + t4;
        af[kb][0] = Au[ar];
        af[kb][1] = Au[ar + 8 * PSTR2];
        af[kb][2] = Au[ar + 4];
        af[kb][3] = Au[ar + 8 * PSTR2 + 4];
    }

    const unsigned wbase = (unsigned)__cvta_generic_to_shared(Ws);
    const int lm = lid >> 3, lr = lid & 7;
    float acc[8][4] = {};
#pragma unroll
    for (int kb = 0; kb < 4; ++kb)
#pragma unroll
        for (int np = 0; np < 4; ++np) {
            unsigned v0, v1, v2, v3;
            unsigned addr = wbase +
                ((kb * 16 + (lm & 1) * 8 + lr) * PSTR + np * 16 + (lm >> 1) * 8) * 2u;
            ldmat4t(v0, v1, v2, v3, addr);
            mma16(acc[2 * np],     af[kb], v0, v1);
            mma16(acc[2 * np + 1], af[kb], v2, v3);
        }

    const long row0 = (r0 + 16 * w + g) * 64;
    const long row1 = row0 + 8 * 64;
#pragma unroll
    for (int nb = 0; nb < 8; ++nb) {
        int c = nb * 8 + 2 * t4;
        float b0v = bb[c], b1v = bb[c + 1];
        *(unsigned*)(dst + row0 + c) = pkh2((acc[nb][0] + b0v) * scale, (acc[nb][1] + b1v) * scale);
        *(unsigned*)(dst + row1 + c) = pkh2((acc[nb][2] + b0v) * scale, (acc[nb][3] + b1v) * scale);
    }
}

// ---------------------------------------------------------------------------
// Kernel 2: fp16 flash attention.
// CTA = 128 q x (b,h); warp w owns q rows [16w,16w+16) x all 64 keys.
// S = Q@K^T (C-frag packs straight into P A-frags: no Pt smem, no shfl).
// V B-frags via ldmatrix.trans. Double-buffered cp.async K/V. 2 CTAs/SM.
// ---------------------------------------------------------------------------
#define SMH_Q 0
#define SMH_K (128 * PSTR)
#define SMH_V (SMH_K + 2 * 64 * PSTR)
#define SMH_TOTAL ((SMH_V + 2 * 64 * PSTR) * 2)   // bytes = 55296

__device__ __forceinline__ void issue_tile_h(unsigned dstb, const __half* gsrc, int tid) {
#pragma unroll
    for (int i = 0; i < 2; ++i) {
        int f = tid + i * 256, r = f >> 3, c = f & 7;
        cp16(dstb + (unsigned)(r * PSTR + c * 8) * 2u, gsrc + (long)r * DMODEL + c * 8);
    }
}

__global__ __launch_bounds__(256, 2) void attn_mma(const int* __restrict__ valid_lens, int S)
{
    extern __shared__ char smc[];
    __half* Qs = (__half*)smc;
    const unsigned smb = (unsigned)__cvta_generic_to_shared(smc);

    const int tid = threadIdx.x, w = tid >> 5, lid = tid & 31;
    const int g = lid >> 2, t4 = lid & 3;
    const int lm = lid >> 3, lr = lid & 7;

    const int h = blockIdx.y, b = blockIdx.z;
    const int s0 = blockIdx.x * 128;
    const int valid = valid_lens[b];
    const long gbase = (long)b * S * DMODEL + h * 64;
    const __half* kg = g_kph + gbase;
    const __half* vg = g_vph + gbase;

    const int nt = (valid + 63) >> 6;

    // G0: Q tile [128 x 64] halfs (1024 16B chunks)
#pragma unroll
    for (int i = 0; i < 4; ++i) {
        int f = tid + i * 256, r = f >> 3, c = f & 7;
        cp16(smb + (unsigned)(SMH_Q + r * PSTR + c * 8) * 2u,
             g_qph + gbase + (long)(s0 + r) * DMODEL + c * 8);
    }
    CP_COMMIT();
    // G1: K0+V0; G2: K1+V1 (maybe empty)
    issue_tile_h(smb + SMH_K * 2u, kg, tid);
    issue_tile_h(smb + SMH_V * 2u, vg, tid);
    CP_COMMIT();
    if (nt > 1) {
        issue_tile_h(smb + (SMH_K + 64 * PSTR) * 2u, kg + 64 * DMODEL, tid);
        issue_tile_h(smb + (SMH_V + 64 * PSTR) * 2u, vg + 64 * DMODEL, tid);
    }
    CP_COMMIT();

    CP_WAIT(2);            // Q ready
    __syncthreads();
    unsigned Qf[4][4];
    {
        const unsigned* Qu = (const unsigned*)Qs;
#pragma unroll
        for (int kb = 0; kb < 4; ++kb) {
            int ar = (w * 16 + g) * PSTR2 + kb * 8 + t4;
            Qf[kb][0] = Qu[ar];
            Qf[kb][1] = Qu[ar + 8 * PSTR2];
            Qf[kb][2] = Qu[ar + 4];
            Qf[kb][3] = Qu[ar + 8 * PSTR2 + 4];
        }
    }
    CP_WAIT(1);            // tile 0 ready
    __syncthreads();

    float octx[8][4] = {};
    float lsum0 = 0.f, lsum1 = 0.f;

    for (int t = 0; t < nt; ++t) {
        const int buf = t & 1;
        const unsigned* Ku = (const unsigned*)((__half*)smc + SMH_K + buf * 64 * PSTR);
        const unsigned vbase = smb + (SMH_V + buf * 64 * PSTR) * 2u;
        const int j0 = t * 64;

        // ---- S = Q @ K^T : 4 kb (e chunks of 16) x 8 nb (key blocks) ----
        float sacc[8][4] = {};
#pragma unroll
        for (int kb = 0; kb < 4; ++kb) {
#pragma unroll
            for (int nb = 0; nb < 8; ++nb) {
                int br = (nb * 8 + g) * PSTR2 + kb * 8 + t4;
                mma16(sacc[nb], Qf[kb], Ku[br], Ku[br + 4]);
            }
        }

        // ---- exp + mask + pack P A-frags directly from C-frags ----
        unsigned pa[4][4];
#pragma unroll
        for (int nb = 0; nb < 8; ++nb) {
            const int keya = j0 + nb * 8 + 2 * t4;
            const int keyb = keya + 1;
            float e0 = keya < valid ? fexp(sacc[nb][0]) : 0.f;
            float e1 = keyb < valid ? fexp(sacc[nb][1]) : 0.f;
            float e2 = keya < valid ? fexp(sacc[nb][2]) : 0.f;
            float e3 = keyb < valid ? fexp(sacc[nb][3]) : 0.f;
            lsum0 += e0 + e1;
            lsum1 += e2 + e3;
            pa[nb >> 1][2 * (nb & 1)]     = pkh2(e0, e1);
            pa[nb >> 1][2 * (nb & 1) + 1] = pkh2(e2, e3);
        }

        // ---- ctx += P @ V : 4 kb (key chunks of 16) x 8 nb (e blocks) ----
#pragma unroll
        for (int kb = 0; kb < 4; ++kb)
#pragma unroll
            for (int np = 0; np < 4; ++np) {
                unsigned v0, v1, v2, v3;
                unsigned addr = vbase +
                    ((kb * 16 + (lm & 1) * 8 + lr) * PSTR + np * 16 + (lm >> 1) * 8) * 2u;
                ldmat4t(v0, v1, v2, v3, addr);
                mma16(octx[2 * np],     pa[kb], v0, v1);
                mma16(octx[2 * np + 1], pa[kb], v2, v3);
            }

        __syncthreads();                 // all warps done with buf
        if (t + 2 < nt) {
            issue_tile_h(smb + (SMH_K + buf * 64 * PSTR) * 2u, kg + (long)(t + 2) * 64 * DMODEL, tid);
            issue_tile_h(smb + (SMH_V + buf * 64 * PSTR) * 2u, vg + (long)(t + 2) * 64 * DMODEL, tid);
        }
        CP_COMMIT();
        CP_WAIT(1);                      // tile t+1 ready
        __syncthreads();
    }

    // ---- epilogue: warp-local softmax denominators, normalize, store fp16 ----
    lsum0 += __shfl_xor_sync(0xffffffffu, lsum0, 1);
    lsum0 += __shfl_xor_sync(0xffffffffu, lsum0, 2);
    lsum1 += __shfl_xor_sync(0xffffffffu, lsum1, 1);
    lsum1 += __shfl_xor_sync(0xffffffffu, lsum1, 2);
    const float inv0 = 1.0f / lsum0;
    const float inv1 = 1.0f / lsum1;
    __half* o0 = g_ctxh + gbase + (long)(s0 + w * 16 + g) * DMODEL;
    __half* o1 = o0 + 8 * DMODEL;
#pragma unroll
    for (int nb = 0; nb < 8; ++nb) {
        int c = nb * 8 + 2 * t4;
        *(unsigned*)(o0 + c) = pkh2(octx[nb][0] * inv0, octx[nb][1] * inv0);
        *(unsigned*)(o1 + c) = pkh2(octx[nb][2] * inv1, octx[nb][3] * inv1);
    }
}

// ---------------------------------------------------------------------------
// Kernel 3: output projection out = ctx @ Wo + bo (fp16 mma, fp32 out).
// CTA: 128 rows x 64 cols, k-loop over 512 in 64-chunks.
// ---------------------------------------------------------------------------
__global__ __launch_bounds__(256) void outp_tc(
    const float* __restrict__ Wo, const float* __restrict__ bo, float* __restrict__ out)
{
    extern __shared__ char smc[];
    __half* As = (__half*)smc;                // [128][72]
    __half* Ws = (__half*)smc + 128 * PSTR;   // [64][72]

    const int tid = threadIdx.x, w = tid >> 5, lid = tid & 31;
    const int g = lid >> 2, t4 = lid & 3;
    const int lm = lid >> 3, lr = lid & 7;
    const long r0 = (long)blockIdx.y * 128;
    const int n0 = blockIdx.x * 64;
    const unsigned wbase = (unsigned)__cvta_generic_to_shared(Ws);

    float acc[8][4] = {};
    for (int k0 = 0; k0 < DMODEL; k0 += 64) {
        if (k0) __syncthreads();
        // stage ctx (already fp16): 128 rows x 8 uint4 chunks
#pragma unroll
        for (int i = 0; i < 4; ++i) {
            int f = tid + i * 256, r = f >> 3, c = f & 7;
            *(uint4*)&As[r * PSTR + c * 8] =
                *(const uint4*)(g_ctxh + (r0 + r) * DMODEL + k0 + c * 8);
        }
        // stage Wo chunk (cvt fp32->fp16)
#pragma unroll
        for (int i = 0; i < 4; ++i) {
            int f = tid + i * 256, r = f >> 4, c = f & 15;
            float4 a = *(const float4*)(Wo + (long)(k0 + r) * DMODEL + n0 + c * 4);
            *(uint2*)&Ws[r * PSTR + c * 4] = make_uint2(pkh2(a.x, a.y), pkh2(a.z, a.w));
        }
        __syncthreads();

        const unsigned* Au = (const unsigned*)As;
#pragma unroll
        for (int kb = 0; kb < 4; ++kb) {
            unsigned af[4];
            int ar = (16 * w + g) * PSTR2 + kb * 8 + t4;
            af[0] = Au[ar];
            af[1] = Au[ar + 8 * PSTR2];
            af[2] = Au[ar + 4];
            af[3] = Au[ar + 8 * PSTR2 + 4];
#pragma unroll
            for (int np = 0; np < 4; ++np) {
                unsigned v0, v1, v2, v3;
                unsigned addr = wbase +
                    ((kb * 16 + (lm & 1) * 8 + lr) * PSTR + np * 16 + (lm >> 1) * 8) * 2u;
                ldmat4t(v0, v1, v2, v3, addr);
                mma16(acc[2 * np],     af, v0, v1);
                mma16(acc[2 * np + 1], af, v2, v3);
            }
        }
    }

    const long row0 = (r0 + 16 * w + g) * DMODEL + n0;
    const long row1 = row0 + 8 * DMODEL;
#pragma unroll
    for (int nb = 0; nb < 8; ++nb) {
        int c = nb * 8 + 2 * t4;
        float b0v = bo[n0 + c], b1v = bo[n0 + c + 1];
        *(float2*)(out + row0 + c) = make_float2(acc[nb][0] + b0v, acc[nb][1] + b1v);
        *(float2*)(out + row1 + c) = make_float2(acc[nb][2] + b0v, acc[nb][3] + b1v);
    }
}

// ---------------------------------------------------------------------------
// launch
// inputs: 0:q 1:k 2:v 3:Wq 4:bq 5:Wk 6:bk 7:Wv 8:bv 9:Wo 10:bo 11:valid_lens 12:max_len
// ---------------------------------------------------------------------------
extern "C" void kernel_launch(void* const* d_in, const int* in_sizes, int n_in,
                              void* d_out, int out_size)
{
    const float* q  = (const float*)d_in[0];
    const float* k  = (const float*)d_in[1];
    const float* v  = (const float*)d_in[2];
    const float* Wq = (const float*)d_in[3];
    const float* bq = (const float*)d_in[4];
    const float* Wk = (const float*)d_in[5];
    const float* bk = (const float*)d_in[6];
    const float* Wv = (const float*)d_in[7];
    const float* bv = (const float*)d_in[8];
    const float* Wo = (const float*)d_in[9];
    const float* bo = (const float*)d_in[10];
    const int* valid_lens = (const int*)d_in[11];
    float* out = (float*)d_out;

    const int B = in_sizes[11];
    const int S = in_sizes[0] / (B * DMODEL);
    const int BS = B * S;

    const int smGemm = (128 * PSTR + 64 * PSTR) * 2;   // 27648 B
    const int smAttn = SMH_TOTAL;                       // 55296 B

    // 1) projections (x viewed as [BS*8, 64] rows)
    cudaFuncSetAttribute(proj_tc, cudaFuncAttributeMaxDynamicSharedMemorySize, smGemm);
    proj_tc<<<dim3(BS * 8 / 128, 3), 256, smGemm>>>(q, k, v, Wq, Wk, Wv, bq, bk, bv);

    // 2) fp16 flash attention (2 CTAs/SM, double-buffered cp.async)
    cudaFuncSetAttribute(attn_mma, cudaFuncAttributeMaxDynamicSharedMemorySize, smAttn);
    attn_mma<<<dim3(S / 128, NHEAD, B), 256, smAttn>>>(valid_lens, S);

    // 3) output projection
    cudaFuncSetAttribute(outp_tc, cudaFuncAttributeMaxDynamicSharedMemorySize, smGemm);
    outp_tc<<<dim3(DMODEL / 64, BS / 128), 256, smGemm>>>(Wo, bo, out);
}

// round 9
// speedup vs baseline: 2.4506x; 1.4062x over previous
#include <cuda_runtime.h>
#include <cuda_fp16.h>
#include <stdint.h>

#define NHEAD 8
#define DMODEL 512
#define MAXELEMS (4*2048*512)

// Scratch (allocation-free rule: __device__ globals) — fp16 activations
__device__ __half g_qph[MAXELEMS];   // pre-scaled by 1/8
__device__ __half g_kph[MAXELEMS];
__device__ __half g_vph[MAXELEMS];
__device__ __half g_ctxh[MAXELEMS];

// ---------------------------------------------------------------------------
// fp16 mma + ldmatrix helpers (legacy path: valid on plain sm_103 target)
// ---------------------------------------------------------------------------
__device__ __forceinline__ void mma16(float c[4], const unsigned a[4],
                                      unsigned b0, unsigned b1) {
    asm volatile("mma.sync.aligned.m16n8k16.row.col.f32.f16.f16.f32 "
                 "{%0,%1,%2,%3}, {%4,%5,%6,%7}, {%8,%9}, {%0,%1,%2,%3};"
                 : "+f"(c[0]), "+f"(c[1]), "+f"(c[2]), "+f"(c[3])
                 : "r"(a[0]), "r"(a[1]), "r"(a[2]), "r"(a[3]), "r"(b0), "r"(b1));
}
__device__ __forceinline__ void ldmat4(unsigned& r0, unsigned& r1,
                                       unsigned& r2, unsigned& r3, unsigned addr) {
    asm volatile("ldmatrix.sync.aligned.m8n8.x4.shared.b16 {%0,%1,%2,%3}, [%4];"
                 : "=r"(r0), "=r"(r1), "=r"(r2), "=r"(r3) : "r"(addr));
}
__device__ __forceinline__ void ldmat4t(unsigned& r0, unsigned& r1,
                                        unsigned& r2, unsigned& r3, unsigned addr) {
    asm volatile("ldmatrix.sync.aligned.m8n8.x4.trans.shared.b16 {%0,%1,%2,%3}, [%4];"
                 : "=r"(r0), "=r"(r1), "=r"(r2), "=r"(r3) : "r"(addr));
}
__device__ __forceinline__ unsigned pkh2(float a, float b) {
    __half2 h = __floats2half2_rn(a, b);
    return *reinterpret_cast<unsigned*>(&h);
}

// cp.async helpers
__device__ __forceinline__ void cp16(unsigned dst, const void* src) {
    asm volatile("cp.async.cg.shared.global [%0], [%1], 16;" :: "r"(dst), "l"(src));
}
#define CP_COMMIT() asm volatile("cp.async.commit_group;" ::: "memory")
#define CP_WAIT(n)  asm volatile("cp.async.wait_group %0;" :: "n"(n) : "memory")

// pane row stride: 72 halfs (36 half2; 36 mod 32 = 4 -> conflict-free frags;
// 144 B rows = 9 x 16B -> ldmatrix-aligned, conflict-free phases)
#define PSTR 72
#define PSTR2 36

// ---------------------------------------------------------------------------
// Kernel 1: projections (x viewed as [BS*8, 64] rows; W shared across heads).
// ---------------------------------------------------------------------------
__global__ __launch_bounds__(256) void proj_tc(
    const float* __restrict__ q, const float* __restrict__ k, const float* __restrict__ v,
    const float* __restrict__ Wq, const float* __restrict__ Wk, const float* __restrict__ Wv,
    const float* __restrict__ bq, const float* __restrict__ bk, const float* __restrict__ bv)
{
    extern __shared__ char smc[];
    __half* As = (__half*)smc;                // [128][72]
    __half* Ws = (__half*)smc + 128 * PSTR;   // [64][72]

    const int tid = threadIdx.x, w = tid >> 5, lid = tid & 31;
    const int g = lid >> 2, t4 = lid & 3;
    const int which = blockIdx.y;
    const float* x  = which == 0 ? q  : which == 1 ? k  : v;
    const float* W  = which == 0 ? Wq : which == 1 ? Wk : Wv;
    const float* bb = which == 0 ? bq : which == 1 ? bk : bv;
    __half* dst = which == 0 ? g_qph : which == 1 ? g_kph : g_vph;
    const float scale = which == 0 ? 0.125f : 1.0f;
    const long r0 = (long)blockIdx.x * 128;

#pragma unroll
    for (int i = 0; i < 8; ++i) {
        int f = tid + i * 256, r = f >> 4, c = f & 15;
        float4 a = *(const float4*)(x + (r0 + r) * 64 + c * 4);
        *(uint2*)&As[r * PSTR + c * 4] = make_uint2(pkh2(a.x, a.y), pkh2(a.z, a.w));
    }
#pragma unroll
    for (int i = 0; i < 4; ++i) {
        int f = tid + i * 256, r = f >> 4, c = f & 15;
        float4 a = *(const float4*)(W + r * 64 + c * 4);
        *(uint2*)&Ws[r * PSTR + c * 4] = make_uint2(pkh2(a.x, a.y), pkh2(a.z, a.w));
    }
    __syncthreads();

    const int lm = lid >> 3, lr = lid & 7;
    const unsigned abase = (unsigned)__cvta_generic_to_shared(As);
    const unsigned wbase = (unsigned)__cvta_generic_to_shared(Ws);

    unsigned af[4][4];
#pragma unroll
    for (int kb = 0; kb < 4; ++kb) {
        unsigned addr = abase +
            ((16 * w + (lm & 1) * 8 + lr) * PSTR + kb * 16 + (lm >> 1) * 8) * 2u;
        ldmat4(af[kb][0], af[kb][1], af[kb][2], af[kb][3], addr);
    }

    float acc[8][4] = {};
#pragma unroll
    for (int kb = 0; kb < 4; ++kb)
#pragma unroll
        for (int np = 0; np < 4; ++np) {
            unsigned v0, v1, v2, v3;
            unsigned addr = wbase +
                ((kb * 16 + (lm & 1) * 8 + lr) * PSTR + np * 16 + (lm >> 1) * 8) * 2u;
            ldmat4t(v0, v1, v2, v3, addr);
            mma16(acc[2 * np],     af[kb], v0, v1);
            mma16(acc[2 * np + 1], af[kb], v2, v3);
        }

    const long row0 = (r0 + 16 * w + g) * 64;
    const long row1 = row0 + 8 * 64;
#pragma unroll
    for (int nb = 0; nb < 8; ++nb) {
        int c = nb * 8 + 2 * t4;
        float b0v = bb[c], b1v = bb[c + 1];
        *(unsigned*)(dst + row0 + c) = pkh2((acc[nb][0] + b0v) * scale, (acc[nb][1] + b1v) * scale);
        *(unsigned*)(dst + row1 + c) = pkh2((acc[nb][2] + b0v) * scale, (acc[nb][3] + b1v) * scale);
    }
}

// ---------------------------------------------------------------------------
// Kernel 2: fp16 flash attention (lean issue stream).
// CTA = 128 q x (b,h); warp w owns q rows [16w,16w+16) x all 64 keys.
// K B-frags + V B-frags via ldmatrix.x4; exp via MUFU __expf; mask checks
// only in the final partial tile. Double-buffered cp.async K/V. 2 CTAs/SM.
// ---------------------------------------------------------------------------
#define SMH_Q 0
#define SMH_K (128 * PSTR)
#define SMH_V (SMH_K + 2 * 64 * PSTR)
#define SMH_TOTAL ((SMH_V + 2 * 64 * PSTR) * 2)   // 55296 B

__device__ __forceinline__ void issue_tile_h(unsigned dstb, const __half* gsrc, int tid) {
#pragma unroll
    for (int i = 0; i < 2; ++i) {
        int f = tid + i * 256, r = f >> 3, c = f & 7;
        cp16(dstb + (unsigned)(r * PSTR + c * 8) * 2u, gsrc + (long)r * DMODEL + c * 8);
    }
}

__global__ __launch_bounds__(256, 2) void attn_mma(const int* __restrict__ valid_lens, int S)
{
    extern __shared__ char smc[];
    const unsigned smb = (unsigned)__cvta_generic_to_shared(smc);

    const int tid = threadIdx.x, w = tid >> 5, lid = tid & 31;
    const int g = lid >> 2, t4 = lid & 3;
    const int lm = lid >> 3, lr = lid & 7;

    const int h = blockIdx.y, b = blockIdx.z;
    const int s0 = blockIdx.x * 128;
    const int valid = valid_lens[b];
    const long gbase = (long)b * S * DMODEL + h * 64;
    const __half* kg = g_kph + gbase;
    const __half* vg = g_vph + gbase;

    const int nt = (valid + 63) >> 6;

    // G0: Q tile [128 x 64]
#pragma unroll
    for (int i = 0; i < 4; ++i) {
        int f = tid + i * 256, r = f >> 3, c = f & 7;
        cp16(smb + (unsigned)(SMH_Q + r * PSTR + c * 8) * 2u,
             g_qph + gbase + (long)(s0 + r) * DMODEL + c * 8);
    }
    CP_COMMIT();
    // G1: K0+V0; G2: K1+V1 (maybe empty)
    issue_tile_h(smb + SMH_K * 2u, kg, tid);
    issue_tile_h(smb + SMH_V * 2u, vg, tid);
    CP_COMMIT();
    if (nt > 1) {
        issue_tile_h(smb + (SMH_K + 64 * PSTR) * 2u, kg + 64 * DMODEL, tid);
        issue_tile_h(smb + (SMH_V + 64 * PSTR) * 2u, vg + 64 * DMODEL, tid);
    }
    CP_COMMIT();

    CP_WAIT(2);            // Q ready
    __syncthreads();
    unsigned Qf[4][4];
#pragma unroll
    for (int kb = 0; kb < 4; ++kb) {
        unsigned addr = smb +
            ((SMH_Q + (w * 16 + (lm & 1) * 8 + lr) * PSTR + kb * 16 + (lm >> 1) * 8)) * 2u;
        ldmat4(Qf[kb][0], Qf[kb][1], Qf[kb][2], Qf[kb][3], addr);
    }
    CP_WAIT(1);            // tile 0 ready
    __syncthreads();

    float octx[8][4] = {};
    float lsum0 = 0.f, lsum1 = 0.f;

    for (int t = 0; t < nt; ++t) {
        const int buf = t & 1;
        const unsigned kbase = smb + (SMH_K + buf * 64 * PSTR) * 2u;
        const unsigned vbase = smb + (SMH_V + buf * 64 * PSTR) * 2u;
        const int j0 = t * 64;
        const bool masked = (t == nt - 1) && (valid & 63);

        // ---- S = Q @ K^T : K b-frags via non-trans ldmatrix.x4 ----
        float sacc[8][4] = {};
#pragma unroll
        for (int kb = 0; kb < 4; ++kb)
#pragma unroll
            for (int np = 0; np < 4; ++np) {
                unsigned k0, k1, k2, k3;
                unsigned addr = kbase +
                    ((np * 16 + (lm & 1) * 8 + lr) * PSTR + kb * 16 + (lm >> 1) * 8) * 2u;
                ldmat4(k0, k1, k2, k3, addr);
                mma16(sacc[2 * np],     Qf[kb], k0, k2);
                mma16(sacc[2 * np + 1], Qf[kb], k1, k3);
            }

        // ---- exp (MUFU) + pack P A-frags; masking only in the tail tile ----
        unsigned pa[4][4];
        if (!masked) {
#pragma unroll
            for (int nb = 0; nb < 8; ++nb) {
                float e0 = __expf(sacc[nb][0]);
                float e1 = __expf(sacc[nb][1]);
                float e2 = __expf(sacc[nb][2]);
                float e3 = __expf(sacc[nb][3]);
                lsum0 += e0 + e1;
                lsum1 += e2 + e3;
                pa[nb >> 1][2 * (nb & 1)]     = pkh2(e0, e1);
                pa[nb >> 1][2 * (nb & 1) + 1] = pkh2(e2, e3);
            }
        } else {
#pragma unroll
            for (int nb = 0; nb < 8; ++nb) {
                const int keya = j0 + nb * 8 + 2 * t4;
                const int keyb = keya + 1;
                float e0 = keya < valid ? __expf(sacc[nb][0]) : 0.f;
                float e1 = keyb < valid ? __expf(sacc[nb][1]) : 0.f;
                float e2 = keya < valid ? __expf(sacc[nb][2]) : 0.f;
                float e3 = keyb < valid ? __expf(sacc[nb][3]) : 0.f;
                lsum0 += e0 + e1;
                lsum1 += e2 + e3;
                pa[nb >> 1][2 * (nb & 1)]     = pkh2(e0, e1);
                pa[nb >> 1][2 * (nb & 1) + 1] = pkh2(e2, e3);
            }
        }

        // ---- ctx += P @ V : V b-frags via trans ldmatrix.x4 ----
#pragma unroll
        for (int kb = 0; kb < 4; ++kb)
#pragma unroll
            for (int np = 0; np < 4; ++np) {
                unsigned v0, v1, v2, v3;
                unsigned addr = vbase +
                    ((kb * 16 + (lm & 1) * 8 + lr) * PSTR + np * 16 + (lm >> 1) * 8) * 2u;
                ldmat4t(v0, v1, v2, v3, addr);
                mma16(octx[2 * np],     pa[kb], v0, v1);
                mma16(octx[2 * np + 1], pa[kb], v2, v3);
            }

        __syncthreads();                 // all warps done with buf
        if (t + 2 < nt) {
            issue_tile_h(smb + (SMH_K + buf * 64 * PSTR) * 2u, kg + (long)(t + 2) * 64 * DMODEL, tid);
            issue_tile_h(smb + (SMH_V + buf * 64 * PSTR) * 2u, vg + (long)(t + 2) * 64 * DMODEL, tid);
        }
        CP_COMMIT();
        CP_WAIT(1);                      // tile t+1 ready
        __syncthreads();
    }

    // ---- epilogue: warp-local softmax denominators, normalize, store fp16 ----
    lsum0 += __shfl_xor_sync(0xffffffffu, lsum0, 1);
    lsum0 += __shfl_xor_sync(0xffffffffu, lsum0, 2);
    lsum1 += __shfl_xor_sync(0xffffffffu, lsum1, 1);
    lsum1 += __shfl_xor_sync(0xffffffffu, lsum1, 2);
    const float inv0 = 1.0f / lsum0;
    const float inv1 = 1.0f / lsum1;
    __half* o0 = g_ctxh + gbase + (long)(s0 + w * 16 + g) * DMODEL;
    __half* o1 = o0 + 8 * DMODEL;
#pragma unroll
    for (int nb = 0; nb < 8; ++nb) {
        int c = nb * 8 + 2 * t4;
        *(unsigned*)(o0 + c) = pkh2(octx[nb][0] * inv0, octx[nb][1] * inv0);
        *(unsigned*)(o1 + c) = pkh2(octx[nb][2] * inv1, octx[nb][3] * inv1);
    }
}

// ---------------------------------------------------------------------------
// Kernel 3: output projection out = ctx @ Wo + bo (fp16 mma, fp32 out).
// ---------------------------------------------------------------------------
__global__ __launch_bounds__(256) void outp_tc(
    const float* __restrict__ Wo, const float* __restrict__ bo, float* __restrict__ out)
{
    extern __shared__ char smc[];
    __half* As = (__half*)smc;                // [128][72]
    __half* Ws = (__half*)smc + 128 * PSTR;   // [64][72]

    const int tid = threadIdx.x, w = tid >> 5, lid = tid & 31;
    const int g = lid >> 2, t4 = lid & 3;
    const int lm = lid >> 3, lr = lid & 7;
    const long r0 = (long)blockIdx.y * 128;
    const int n0 = blockIdx.x * 64;
    const unsigned abase = (unsigned)__cvta_generic_to_shared(As);
    const unsigned wbase = (unsigned)__cvta_generic_to_shared(Ws);

    float acc[8][4] = {};
    for (int k0 = 0; k0 < DMODEL; k0 += 64) {
        if (k0) __syncthreads();
#pragma unroll
        for (int i = 0; i < 4; ++i) {
            int f = tid + i * 256, r = f >> 3, c = f & 7;
            *(uint4*)&As[r * PSTR + c * 8] =
                *(const uint4*)(g_ctxh + (r0 + r) * DMODEL + k0 + c * 8);
        }
#pragma unroll
        for (int i = 0; i < 4; ++i) {
            int f = tid + i * 256, r = f >> 4, c = f & 15;
            float4 a = *(const float4*)(Wo + (long)(k0 + r) * DMODEL + n0 + c * 4);
            *(uint2*)&Ws[r * PSTR + c * 4] = make_uint2(pkh2(a.x, a.y), pkh2(a.z, a.w));
        }
        __syncthreads();

#pragma unroll
        for (int kb = 0; kb < 4; ++kb) {
            unsigned af[4];
            unsigned aaddr = abase +
                ((16 * w + (lm & 1) * 8 + lr) * PSTR + kb * 16 + (lm >> 1) * 8) * 2u;
            ldmat4(af[0], af[1], af[2], af[3], aaddr);
#pragma unroll
            for (int np = 0; np < 4; ++np) {
                unsigned v0, v1, v2, v3;
                unsigned addr = wbase +
                    ((kb * 16 + (lm & 1) * 8 + lr) * PSTR + np * 16 + (lm >> 1) * 8) * 2u;
                ldmat4t(v0, v1, v2, v3, addr);
                mma16(acc[2 * np],     af, v0, v1);
                mma16(acc[2 * np + 1], af, v2, v3);
            }
        }
    }

    const long row0 = (r0 + 16 * w + g) * DMODEL + n0;
    const long row1 = row0 + 8 * DMODEL;
#pragma unroll
    for (int nb = 0; nb < 8; ++nb) {
        int c = nb * 8 + 2 * t4;
        float b0v = bo[n0 + c], b1v = bo[n0 + c + 1];
        *(float2*)(out + row0 + c) = make_float2(acc[nb][0] + b0v, acc[nb][1] + b1v);
        *(float2*)(out + row1 + c) = make_float2(acc[nb][2] + b0v, acc[nb][3] + b1v);
    }
}

// ---------------------------------------------------------------------------
// launch
// inputs: 0:q 1:k 2:v 3:Wq 4:bq 5:Wk 6:bk 7:Wv 8:bv 9:Wo 10:bo 11:valid_lens 12:max_len
// ---------------------------------------------------------------------------
extern "C" void kernel_launch(void* const* d_in, const int* in_sizes, int n_in,
                              void* d_out, int out_size)
{
    const float* q  = (const float*)d_in[0];
    const float* k  = (const float*)d_in[1];
    const float* v  = (const float*)d_in[2];
    const float* Wq = (const float*)d_in[3];
    const float* bq = (const float*)d_in[4];
    const float* Wk = (const float*)d_in[5];
    const float* bk = (const float*)d_in[6];
    const float* Wv = (const float*)d_in[7];
    const float* bv = (const float*)d_in[8];
    const float* Wo = (const float*)d_in[9];
    const float* bo = (const float*)d_in[10];
    const int* valid_lens = (const int*)d_in[11];
    float* out = (float*)d_out;

    const int B = in_sizes[11];
    const int S = in_sizes[0] / (B * DMODEL);
    const int BS = B * S;

    const int smGemm = (128 * PSTR + 64 * PSTR) * 2;   // 27648 B
    const int smAttn = SMH_TOTAL;                       // 55296 B

    // 1) projections (x viewed as [BS*8, 64] rows)
    cudaFuncSetAttribute(proj_tc, cudaFuncAttributeMaxDynamicSharedMemorySize, smGemm);
    proj_tc<<<dim3(BS * 8 / 128, 3), 256, smGemm>>>(q, k, v, Wq, Wk, Wv, bq, bk, bv);

    // 2) fp16 flash attention (2 CTAs/SM, double-buffered cp.async)
    cudaFuncSetAttribute(attn_mma, cudaFuncAttributeMaxDynamicSharedMemorySize, smAttn);
    attn_mma<<<dim3(S / 128, NHEAD, B), 256, smAttn>>>(valid_lens, S);

    // 3) output projection
    cudaFuncSetAttribute(outp_tc, cudaFuncAttributeMaxDynamicSharedMemorySize, smGemm);
    outp_tc<<<dim3(DMODEL / 64, BS / 128), 256, smGemm>>>(Wo, bo, out);
}

// round 10
// speedup vs baseline: 2.7091x; 1.1055x over previous
#include <cuda_runtime.h>
#include <cuda_fp16.h>
#include <stdint.h>

#define NHEAD 8
#define DMODEL 512
#define MAXELEMS (4*2048*512)

// Scratch (allocation-free rule: __device__ globals) — fp16 activations
__device__ __half g_qph[MAXELEMS];   // pre-scaled by 0.125*log2(e)
__device__ __half g_kph[MAXELEMS];
__device__ __half g_vph[MAXELEMS];
__device__ __half g_ctxh[MAXELEMS];
__device__ __half g_woh[DMODEL * DMODEL];

// ---------------------------------------------------------------------------
// fp16 mma + ldmatrix helpers (legacy path: valid on plain sm_103 target)
// ---------------------------------------------------------------------------
__device__ __forceinline__ void mma16(float c[4], const unsigned a[4],
                                      unsigned b0, unsigned b1) {
    asm volatile("mma.sync.aligned.m16n8k16.row.col.f32.f16.f16.f32 "
                 "{%0,%1,%2,%3}, {%4,%5,%6,%7}, {%8,%9}, {%0,%1,%2,%3};"
                 : "+f"(c[0]), "+f"(c[1]), "+f"(c[2]), "+f"(c[3])
                 : "r"(a[0]), "r"(a[1]), "r"(a[2]), "r"(a[3]), "r"(b0), "r"(b1));
}
__device__ __forceinline__ void ldmat4(unsigned& r0, unsigned& r1,
                                       unsigned& r2, unsigned& r3, unsigned addr) {
    asm volatile("ldmatrix.sync.aligned.m8n8.x4.shared.b16 {%0,%1,%2,%3}, [%4];"
                 : "=r"(r0), "=r"(r1), "=r"(r2), "=r"(r3) : "r"(addr));
}
__device__ __forceinline__ void ldmat4t(unsigned& r0, unsigned& r1,
                                        unsigned& r2, unsigned& r3, unsigned addr) {
    asm volatile("ldmatrix.sync.aligned.m8n8.x4.trans.shared.b16 {%0,%1,%2,%3}, [%4];"
                 : "=r"(r0), "=r"(r1), "=r"(r2), "=r"(r3) : "r"(addr));
}
__device__ __forceinline__ unsigned pkh2(float a, float b) {
    __half2 h = __floats2half2_rn(a, b);
    return *reinterpret_cast<unsigned*>(&h);
}
__device__ __forceinline__ unsigned ex2h2(unsigned x) {
    unsigned r;
    asm("ex2.approx.f16x2 %0, %1;" : "=r"(r) : "r"(x));
    return r;
}
__device__ __forceinline__ unsigned hmul2u(unsigned a, unsigned b) {
    __half2 r = __hmul2(*reinterpret_cast<__half2*>(&a), *reinterpret_cast<__half2*>(&b));
    return *reinterpret_cast<unsigned*>(&r);
}
#define ONES2 0x3C003C00u   // half2(1.0, 1.0)

// cp.async helpers
__device__ __forceinline__ void cp16(unsigned dst, const void* src) {
    asm volatile("cp.async.cg.shared.global [%0], [%1], 16;" :: "r"(dst), "l"(src));
}
#define CP_COMMIT() asm volatile("cp.async.commit_group;" ::: "memory")
#define CP_WAIT(n)  asm volatile("cp.async.wait_group %0;" :: "n"(n) : "memory")

// pane row stride: 72 halfs (36 half2; 36 mod 32 = 4 -> conflict-free frags;
// 144 B rows = 9 x 16B -> ldmatrix-aligned, conflict-free phases)
#define PSTR 72
#define PSTR2 36

// ---------------------------------------------------------------------------
// Kernel 0: one-time Wo fp32 -> fp16 (512x512 = 512 KB out)
// ---------------------------------------------------------------------------
__global__ __launch_bounds__(256) void cvt_wo(const float* __restrict__ Wo) {
    int i = (blockIdx.x * 256 + threadIdx.x) * 4;
    float4 a = *(const float4*)(Wo + i);
    *(uint2*)&g_woh[i] = make_uint2(pkh2(a.x, a.y), pkh2(a.z, a.w));
}

// ---------------------------------------------------------------------------
// Kernel 1: projections (x viewed as [BS*8, 64] rows; W shared across heads).
// q output pre-scaled by 0.125*log2(e) so attention scores are base-2 ready.
// ---------------------------------------------------------------------------
__global__ __launch_bounds__(256) void proj_tc(
    const float* __restrict__ q, const float* __restrict__ k, const float* __restrict__ v,
    const float* __restrict__ Wq, const float* __restrict__ Wk, const float* __restrict__ Wv,
    const float* __restrict__ bq, const float* __restrict__ bk, const float* __restrict__ bv)
{
    extern __shared__ char smc[];
    __half* As = (__half*)smc;                // [128][72]
    __half* Ws = (__half*)smc + 128 * PSTR;   // [64][72]

    const int tid = threadIdx.x, w = tid >> 5, lid = tid & 31;
    const int g = lid >> 2, t4 = lid & 3;
    const int which = blockIdx.y;
    const float* x  = which == 0 ? q  : which == 1 ? k  : v;
    const float* W  = which == 0 ? Wq : which == 1 ? Wk : Wv;
    const float* bb = which == 0 ? bq : which == 1 ? bk : bv;
    __half* dst = which == 0 ? g_qph : which == 1 ? g_kph : g_vph;
    const float scale = which == 0 ? 0.125f * 1.4426950408889634f : 1.0f;
    const long r0 = (long)blockIdx.x * 128;

#pragma unroll
    for (int i = 0; i < 8; ++i) {
        int f = tid + i * 256, r = f >> 4, c = f & 15;
        float4 a = *(const float4*)(x + (r0 + r) * 64 + c * 4);
        *(uint2*)&As[r * PSTR + c * 4] = make_uint2(pkh2(a.x, a.y), pkh2(a.z, a.w));
    }
#pragma unroll
    for (int i = 0; i < 4; ++i) {
        int f = tid + i * 256, r = f >> 4, c = f & 15;
        float4 a = *(const float4*)(W + r * 64 + c * 4);
        *(uint2*)&Ws[r * PSTR + c * 4] = make_uint2(pkh2(a.x, a.y), pkh2(a.z, a.w));
    }
    __syncthreads();

    const int lm = lid >> 3, lr = lid & 7;
    const unsigned abase = (unsigned)__cvta_generic_to_shared(As);
    const unsigned wbase = (unsigned)__cvta_generic_to_shared(Ws);

    unsigned af[4][4];
#pragma unroll
    for (int kb = 0; kb < 4; ++kb) {
        unsigned addr = abase +
            ((16 * w + (lm & 1) * 8 + lr) * PSTR + kb * 16 + (lm >> 1) * 8) * 2u;
        ldmat4(af[kb][0], af[kb][1], af[kb][2], af[kb][3], addr);
    }

    float acc[8][4] = {};
#pragma unroll
    for (int kb = 0; kb < 4; ++kb)
#pragma unroll
        for (int np = 0; np < 4; ++np) {
            unsigned v0, v1, v2, v3;
            unsigned addr = wbase +
                ((kb * 16 + (lm & 1) * 8 + lr) * PSTR + np * 16 + (lm >> 1) * 8) * 2u;
            ldmat4t(v0, v1, v2, v3, addr);
            mma16(acc[2 * np],     af[kb], v0, v1);
            mma16(acc[2 * np + 1], af[kb], v2, v3);
        }

    const long row0 = (r0 + 16 * w + g) * 64;
    const long row1 = row0 + 8 * 64;
#pragma unroll
    for (int nb = 0; nb < 8; ++nb) {
        int c = nb * 8 + 2 * t4;
        float b0v = bb[c], b1v = bb[c + 1];
        *(unsigned*)(dst + row0 + c) = pkh2((acc[nb][0] + b0v) * scale, (acc[nb][1] + b1v) * scale);
        *(unsigned*)(dst + row1 + c) = pkh2((acc[nb][2] + b0v) * scale, (acc[nb][3] + b1v) * scale);
    }
}

// ---------------------------------------------------------------------------
// Kernel 2: fp16 flash attention (minimal issue stream).
// exp = ex2.approx.f16x2 on packed scores (log2e folded into Q scale);
// softmax denominators accumulated by 4 extra mma with an all-ones B.
// K/V B-frags via ldmatrix.x4. Double-buffered cp.async K/V. 2 CTAs/SM.
// ---------------------------------------------------------------------------
#define SMH_Q 0
#define SMH_K (128 * PSTR)
#define SMH_V (SMH_K + 2 * 64 * PSTR)
#define SMH_TOTAL ((SMH_V + 2 * 64 * PSTR) * 2)   // 55296 B

__device__ __forceinline__ void issue_tile_h(unsigned dstb, const __half* gsrc, int tid) {
#pragma unroll
    for (int i = 0; i < 2; ++i) {
        int f = tid + i * 256, r = f >> 3, c = f & 7;
        cp16(dstb + (unsigned)(r * PSTR + c * 8) * 2u, gsrc + (long)r * DMODEL + c * 8);
    }
}

__global__ __launch_bounds__(256, 2) void attn_mma(const int* __restrict__ valid_lens, int S)
{
    extern __shared__ char smc[];
    const unsigned smb = (unsigned)__cvta_generic_to_shared(smc);

    const int tid = threadIdx.x, w = tid >> 5, lid = tid & 31;
    const int g = lid >> 2, t4 = lid & 3;
    const int lm = lid >> 3, lr = lid & 7;

    const int h = blockIdx.y, b = blockIdx.z;
    const int s0 = blockIdx.x * 128;
    const int valid = valid_lens[b];
    const long gbase = (long)b * S * DMODEL + h * 64;
    const __half* kg = g_kph + gbase;
    const __half* vg = g_vph + gbase;

    const int nt = (valid + 63) >> 6;

    // G0: Q tile [128 x 64]
#pragma unroll
    for (int i = 0; i < 4; ++i) {
        int f = tid + i * 256, r = f >> 3, c = f & 7;
        cp16(smb + (unsigned)(SMH_Q + r * PSTR + c * 8) * 2u,
             g_qph + gbase + (long)(s0 + r) * DMODEL + c * 8);
    }
    CP_COMMIT();
    // G1: K0+V0; G2: K1+V1 (maybe empty)
    issue_tile_h(smb + SMH_K * 2u, kg, tid);
    issue_tile_h(smb + SMH_V * 2u, vg, tid);
    CP_COMMIT();
    if (nt > 1) {
        issue_tile_h(smb + (SMH_K + 64 * PSTR) * 2u, kg + 64 * DMODEL, tid);
        issue_tile_h(smb + (SMH_V + 64 * PSTR) * 2u, vg + 64 * DMODEL, tid);
    }
    CP_COMMIT();

    CP_WAIT(2);            // Q ready
    __syncthreads();
    unsigned Qf[4][4];
#pragma unroll
    for (int kb = 0; kb < 4; ++kb) {
        unsigned addr = smb +
            ((SMH_Q + (w * 16 + (lm & 1) * 8 + lr) * PSTR + kb * 16 + (lm >> 1) * 8)) * 2u;
        ldmat4(Qf[kb][0], Qf[kb][1], Qf[kb][2], Qf[kb][3], addr);
    }
    CP_WAIT(1);            // tile 0 ready
    __syncthreads();

    float octx[8][4] = {};
    float lacc[4] = {};    // softmax denominators via P @ ones

    for (int t = 0; t < nt; ++t) {
        const int buf = t & 1;
        const unsigned kbase = smb + (SMH_K + buf * 64 * PSTR) * 2u;
        const unsigned vbase = smb + (SMH_V + buf * 64 * PSTR) * 2u;
        const int j0 = t * 64;
        const bool masked = (t == nt - 1) && (valid & 63);

        // ---- S = Q @ K^T (scores arrive pre-multiplied by log2e) ----
        float sacc[8][4] = {};
#pragma unroll
        for (int kb = 0; kb < 4; ++kb)
#pragma unroll
            for (int np = 0; np < 4; ++np) {
                unsigned k0, k1, k2, k3;
                unsigned addr = kbase +
                    ((np * 16 + (lm & 1) * 8 + lr) * PSTR + kb * 16 + (lm >> 1) * 8) * 2u;
                ldmat4(k0, k1, k2, k3, addr);
                mma16(sacc[2 * np],     Qf[kb], k0, k2);
                mma16(sacc[2 * np + 1], Qf[kb], k1, k3);
            }

        // ---- P = 2^S via ex2.f16x2; pack directly into A-frags ----
        unsigned pa[4][4];
        if (!masked) {
#pragma unroll
            for (int nb = 0; nb < 8; ++nb) {
                pa[nb >> 1][2 * (nb & 1)]     = ex2h2(pkh2(sacc[nb][0], sacc[nb][1]));
                pa[nb >> 1][2 * (nb & 1) + 1] = ex2h2(pkh2(sacc[nb][2], sacc[nb][3]));
            }
        } else {
#pragma unroll
            for (int nb = 0; nb < 8; ++nb) {
                const int keya = j0 + nb * 8 + 2 * t4;
                const unsigned m = (keya < valid ? 0x00003C00u : 0u) |
                                   (keya + 1 < valid ? 0x3C000000u : 0u);
                pa[nb >> 1][2 * (nb & 1)]     = hmul2u(ex2h2(pkh2(sacc[nb][0], sacc[nb][1])), m);
                pa[nb >> 1][2 * (nb & 1) + 1] = hmul2u(ex2h2(pkh2(sacc[nb][2], sacc[nb][3])), m);
            }
        }

        // ---- l += P @ ones (row sums, fp32, accumulated across tiles) ----
#pragma unroll
        for (int kb = 0; kb < 4; ++kb)
            mma16(lacc, pa[kb], ONES2, ONES2);

        // ---- ctx += P @ V ----
#pragma unroll
        for (int kb = 0; kb < 4; ++kb)
#pragma unroll
            for (int np = 0; np < 4; ++np) {
                unsigned v0, v1, v2, v3;
                unsigned addr = vbase +
                    ((kb * 16 + (lm & 1) * 8 + lr) * PSTR + np * 16 + (lm >> 1) * 8) * 2u;
                ldmat4t(v0, v1, v2, v3, addr);
                mma16(octx[2 * np],     pa[kb], v0, v1);
                mma16(octx[2 * np + 1], pa[kb], v2, v3);
            }

        __syncthreads();                 // all warps done with buf
        if (t + 2 < nt) {
            issue_tile_h(smb + (SMH_K + buf * 64 * PSTR) * 2u, kg + (long)(t + 2) * 64 * DMODEL, tid);
            issue_tile_h(smb + (SMH_V + buf * 64 * PSTR) * 2u, vg + (long)(t + 2) * 64 * DMODEL, tid);
        }
        CP_COMMIT();
        CP_WAIT(1);                      // tile t+1 ready
        __syncthreads();
    }

    // ---- epilogue: normalize (denominators already reduced by mma) ----
    const float inv0 = 1.0f / lacc[0];
    const float inv1 = 1.0f / lacc[2];
    __half* o0 = g_ctxh + gbase + (long)(s0 + w * 16 + g) * DMODEL;
    __half* o1 = o0 + 8 * DMODEL;
#pragma unroll
    for (int nb = 0; nb < 8; ++nb) {
        int c = nb * 8 + 2 * t4;
        *(unsigned*)(o0 + c) = pkh2(octx[nb][0] * inv0, octx[nb][1] * inv0);
        *(unsigned*)(o1 + c) = pkh2(octx[nb][2] * inv1, octx[nb][3] * inv1);
    }
}

// ---------------------------------------------------------------------------
// Kernel 3: output projection out = ctx @ Wo + bo (fp16 mma, fp32 out).
// Wo pre-converted to fp16 (cvt_wo) -> staging is raw uint4 copies.
// ---------------------------------------------------------------------------
__global__ __launch_bounds__(256) void outp_tc(
    const float* __restrict__ bo, float* __restrict__ out)
{
    extern __shared__ char smc[];
    __half* As = (__half*)smc;                // [128][72]
    __half* Ws = (__half*)smc + 128 * PSTR;   // [64][72]

    const int tid = threadIdx.x, w = tid >> 5, lid = tid & 31;
    const int g = lid >> 2, t4 = lid & 3;
    const int lm = lid >> 3, lr = lid & 7;
    const long r0 = (long)blockIdx.y * 128;
    const int n0 = blockIdx.x * 64;
    const unsigned abase = (unsigned)__cvta_generic_to_shared(As);
    const unsigned wbase = (unsigned)__cvta_generic_to_shared(Ws);

    float acc[8][4] = {};
    for (int k0 = 0; k0 < DMODEL; k0 += 64) {
        if (k0) __syncthreads();
#pragma unroll
        for (int i = 0; i < 4; ++i) {
            int f = tid + i * 256, r = f >> 3, c = f & 7;
            *(uint4*)&As[r * PSTR + c * 8] =
                *(const uint4*)(g_ctxh + (r0 + r) * DMODEL + k0 + c * 8);
        }
#pragma unroll
        for (int i = 0; i < 2; ++i) {
            int f = tid + i * 256, r = f >> 3, c = f & 7;
            *(uint4*)&Ws[r * PSTR + c * 8] =
                *(const uint4*)(g_woh + (long)(k0 + r) * DMODEL + n0 + c * 8);
        }
        __syncthreads();

#pragma unroll
        for (int kb = 0; kb < 4; ++kb) {
            unsigned af[4];
            unsigned aaddr = abase +
                ((16 * w + (lm & 1) * 8 + lr) * PSTR + kb * 16 + (lm >> 1) * 8) * 2u;
            ldmat4(af[0], af[1], af[2], af[3], aaddr);
#pragma unroll
            for (int np = 0; np < 4; ++np) {
                unsigned v0, v1, v2, v3;
                unsigned addr = wbase +
                    ((kb * 16 + (lm & 1) * 8 + lr) * PSTR + np * 16 + (lm >> 1) * 8) * 2u;
                ldmat4t(v0, v1, v2, v3, addr);
                mma16(acc[2 * np],     af, v0, v1);
                mma16(acc[2 * np + 1], af, v2, v3);
            }
        }
    }

    const long row0 = (r0 + 16 * w + g) * DMODEL + n0;
    const long row1 = row0 + 8 * DMODEL;
#pragma unroll
    for (int nb = 0; nb < 8; ++nb) {
        int c = nb * 8 + 2 * t4;
        float b0v = bo[n0 + c], b1v = bo[n0 + c + 1];
        *(float2*)(out + row0 + c) = make_float2(acc[nb][0] + b0v, acc[nb][1] + b1v);
        *(float2*)(out + row1 + c) = make_float2(acc[nb][2] + b0v, acc[nb][3] + b1v);
    }
}

// ---------------------------------------------------------------------------
// launch
// inputs: 0:q 1:k 2:v 3:Wq 4:bq 5:Wk 6:bk 7:Wv 8:bv 9:Wo 10:bo 11:valid_lens 12:max_len
// ---------------------------------------------------------------------------
extern "C" void kernel_launch(void* const* d_in, const int* in_sizes, int n_in,
                              void* d_out, int out_size)
{
    const float* q  = (const float*)d_in[0];
    const float* k  = (const float*)d_in[1];
    const float* v  = (const float*)d_in[2];
    const float* Wq = (const float*)d_in[3];
    const float* bq = (const float*)d_in[4];
    const float* Wk = (const float*)d_in[5];
    const float* bk = (const float*)d_in[6];
    const float* Wv = (const float*)d_in[7];
    const float* bv = (const float*)d_in[8];
    const float* Wo = (const float*)d_in[9];
    const float* bo = (const float*)d_in[10];
    const int* valid_lens = (const int*)d_in[11];
    float* out = (float*)d_out;

    const int B = in_sizes[11];
    const int S = in_sizes[0] / (B * DMODEL);
    const int BS = B * S;

    const int smGemm = (128 * PSTR + 64 * PSTR) * 2;   // 27648 B
    const int smAttn = SMH_TOTAL;                       // 55296 B

    // 0) Wo -> fp16 (one-time per launch; overlaps with proj on the GPU)
    cvt_wo<<<DMODEL * DMODEL / 1024, 256>>>(Wo);

    // 1) projections (x viewed as [BS*8, 64] rows)
    cudaFuncSetAttribute(proj_tc, cudaFuncAttributeMaxDynamicSharedMemorySize, smGemm);
    proj_tc<<<dim3(BS * 8 / 128, 3), 256, smGemm>>>(q, k, v, Wq, Wk, Wv, bq, bk, bv);

    // 2) fp16 flash attention (2 CTAs/SM, double-buffered cp.async)
    cudaFuncSetAttribute(attn_mma, cudaFuncAttributeMaxDynamicSharedMemorySize, smAttn);
    attn_mma<<<dim3(S / 128, NHEAD, B), 256, smAttn>>>(valid_lens, S);

    // 3) output projection
    cudaFuncSetAttribute(outp_tc, cudaFuncAttributeMaxDynamicSharedMemorySize, smGemm);
    outp_tc<<<dim3(DMODEL / 64, BS / 128), 256, smGemm>>>(bo, out);
}

// round 11
// speedup vs baseline: 2.7664x; 1.0212x over previous
#include <cuda_runtime.h>
#include <cuda_fp16.h>
#include <stdint.h>

#define NHEAD 8
#define DMODEL 512
#define MAXELEMS (4*2048*512)

// Scratch (allocation-free rule: __device__ globals) — fp16 activations
__device__ __half g_qph[MAXELEMS];   // pre-scaled by 0.125*log2(e)
__device__ __half g_kph[MAXELEMS];
__device__ __half g_vph[MAXELEMS];
__device__ __half g_ctxh[MAXELEMS];
__device__ __half g_woh[DMODEL * DMODEL];

// ---------------------------------------------------------------------------
// fp16 mma + ldmatrix helpers (legacy path: valid on plain sm_103 target)
// ---------------------------------------------------------------------------
__device__ __forceinline__ void mma16(float c[4], const unsigned a[4],
                                      unsigned b0, unsigned b1) {
    asm volatile("mma.sync.aligned.m16n8k16.row.col.f32.f16.f16.f32 "
                 "{%0,%1,%2,%3}, {%4,%5,%6,%7}, {%8,%9}, {%0,%1,%2,%3};"
                 : "+f"(c[0]), "+f"(c[1]), "+f"(c[2]), "+f"(c[3])
                 : "r"(a[0]), "r"(a[1]), "r"(a[2]), "r"(a[3]), "r"(b0), "r"(b1));
}
__device__ __forceinline__ void ldmat4(unsigned& r0, unsigned& r1,
                                       unsigned& r2, unsigned& r3, unsigned addr) {
    asm volatile("ldmatrix.sync.aligned.m8n8.x4.shared.b16 {%0,%1,%2,%3}, [%4];"
                 : "=r"(r0), "=r"(r1), "=r"(r2), "=r"(r3) : "r"(addr));
}
__device__ __forceinline__ void ldmat4t(unsigned& r0, unsigned& r1,
                                        unsigned& r2, unsigned& r3, unsigned addr) {
    asm volatile("ldmatrix.sync.aligned.m8n8.x4.trans.shared.b16 {%0,%1,%2,%3}, [%4];"
                 : "=r"(r0), "=r"(r1), "=r"(r2), "=r"(r3) : "r"(addr));
}
__device__ __forceinline__ unsigned pkh2(float a, float b) {
    __half2 h = __floats2half2_rn(a, b);
    return *reinterpret_cast<unsigned*>(&h);
}
__device__ __forceinline__ unsigned ex2h2(unsigned x) {
    unsigned r;
    asm("ex2.approx.f16x2 %0, %1;" : "=r"(r) : "r"(x));
    return r;
}
__device__ __forceinline__ unsigned hmul2u(unsigned a, unsigned b) {
    __half2 r = __hmul2(*reinterpret_cast<__half2*>(&a), *reinterpret_cast<__half2*>(&b));
    return *reinterpret_cast<unsigned*>(&r);
}
#define ONES2 0x3C003C00u   // half2(1.0, 1.0)

// cp.async helpers
__device__ __forceinline__ void cp16(unsigned dst, const void* src) {
    asm volatile("cp.async.cg.shared.global [%0], [%1], 16;" :: "r"(dst), "l"(src));
}
#define CP_COMMIT() asm volatile("cp.async.commit_group;" ::: "memory")
#define CP_WAIT(n)  asm volatile("cp.async.wait_group %0;" :: "n"(n) : "memory")

// pane row stride: 72 halfs (36 half2; 36 mod 32 = 4 -> conflict-free frags;
// 144 B rows = 9 x 16B -> ldmatrix-aligned, conflict-free phases)
#define PSTR 72
#define PSTR2 36

// ---------------------------------------------------------------------------
// Kernel 0: one-time Wo fp32 -> fp16 (512x512 = 512 KB out)
// ---------------------------------------------------------------------------
__global__ __launch_bounds__(256) void cvt_wo(const float* __restrict__ Wo) {
    int i = (blockIdx.x * 256 + threadIdx.x) * 4;
    float4 a = *(const float4*)(Wo + i);
    *(uint2*)&g_woh[i] = make_uint2(pkh2(a.x, a.y), pkh2(a.z, a.w));
}

// ---------------------------------------------------------------------------
// Kernel 1: projections (x viewed as [BS*8, 64] rows; W shared across heads).
// q output pre-scaled by 0.125*log2(e) so attention scores are base-2 ready.
// ---------------------------------------------------------------------------
__global__ __launch_bounds__(256) void proj_tc(
    const float* __restrict__ q, const float* __restrict__ k, const float* __restrict__ v,
    const float* __restrict__ Wq, const float* __restrict__ Wk, const float* __restrict__ Wv,
    const float* __restrict__ bq, const float* __restrict__ bk, const float* __restrict__ bv)
{
    extern __shared__ char smc[];
    __half* As = (__half*)smc;                // [128][72]
    __half* Ws = (__half*)smc + 128 * PSTR;   // [64][72]

    const int tid = threadIdx.x, w = tid >> 5, lid = tid & 31;
    const int g = lid >> 2, t4 = lid & 3;
    const int which = blockIdx.y;
    const float* x  = which == 0 ? q  : which == 1 ? k  : v;
    const float* W  = which == 0 ? Wq : which == 1 ? Wk : Wv;
    const float* bb = which == 0 ? bq : which == 1 ? bk : bv;
    __half* dst = which == 0 ? g_qph : which == 1 ? g_kph : g_vph;
    const float scale = which == 0 ? 0.125f * 1.4426950408889634f : 1.0f;
    const long r0 = (long)blockIdx.x * 128;

#pragma unroll
    for (int i = 0; i < 8; ++i) {
        int f = tid + i * 256, r = f >> 4, c = f & 15;
        float4 a = *(const float4*)(x + (r0 + r) * 64 + c * 4);
        *(uint2*)&As[r * PSTR + c * 4] = make_uint2(pkh2(a.x, a.y), pkh2(a.z, a.w));
    }
#pragma unroll
    for (int i = 0; i < 4; ++i) {
        int f = tid + i * 256, r = f >> 4, c = f & 15;
        float4 a = *(const float4*)(W + r * 64 + c * 4);
        *(uint2*)&Ws[r * PSTR + c * 4] = make_uint2(pkh2(a.x, a.y), pkh2(a.z, a.w));
    }
    __syncthreads();

    const int lm = lid >> 3, lr = lid & 7;
    const unsigned abase = (unsigned)__cvta_generic_to_shared(As);
    const unsigned wbase = (unsigned)__cvta_generic_to_shared(Ws);

    unsigned af[4][4];
#pragma unroll
    for (int kb = 0; kb < 4; ++kb) {
        unsigned addr = abase +
            ((16 * w + (lm & 1) * 8 + lr) * PSTR + kb * 16 + (lm >> 1) * 8) * 2u;
        ldmat4(af[kb][0], af[kb][1], af[kb][2], af[kb][3], addr);
    }

    float acc[8][4] = {};
#pragma unroll
    for (int kb = 0; kb < 4; ++kb)
#pragma unroll
        for (int np = 0; np < 4; ++np) {
            unsigned v0, v1, v2, v3;
            unsigned addr = wbase +
                ((kb * 16 + (lm & 1) * 8 + lr) * PSTR + np * 16 + (lm >> 1) * 8) * 2u;
            ldmat4t(v0, v1, v2, v3, addr);
            mma16(acc[2 * np],     af[kb], v0, v1);
            mma16(acc[2 * np + 1], af[kb], v2, v3);
        }

    const long row0 = (r0 + 16 * w + g) * 64;
    const long row1 = row0 + 8 * 64;
#pragma unroll
    for (int nb = 0; nb < 8; ++nb) {
        int c = nb * 8 + 2 * t4;
        float b0v = bb[c], b1v = bb[c + 1];
        *(unsigned*)(dst + row0 + c) = pkh2((acc[nb][0] + b0v) * scale, (acc[nb][1] + b1v) * scale);
        *(unsigned*)(dst + row1 + c) = pkh2((acc[nb][2] + b0v) * scale, (acc[nb][3] + b1v) * scale);
    }
}

// ---------------------------------------------------------------------------
// Kernel 2: fp16 flash attention, triple-buffered K/V, ONE barrier per tile.
// exp = ex2.approx.f16x2 (log2e folded into Q); l via P@ones mma. 2 CTAs/SM.
// smem: Q (9216 h) + 3 slots x (K 64x72 + V 64x72) = 36864 halfs = 73728 B.
// ---------------------------------------------------------------------------
#define SMH_Q 0
#define SMH_SLOT (2 * 64 * PSTR)               // 9216 halfs per slot (K+V)
#define SMH_KV (128 * PSTR)                    // slots start after Q
#define SMH_TOTAL ((SMH_KV + 3 * SMH_SLOT) * 2)  // 73728 B

__device__ __forceinline__ void issue_tile_h(unsigned dstb, const __half* gsrc, int tid) {
#pragma unroll
    for (int i = 0; i < 2; ++i) {
        int f = tid + i * 256, r = f >> 3, c = f & 7;
        cp16(dstb + (unsigned)(r * PSTR + c * 8) * 2u, gsrc + (long)r * DMODEL + c * 8);
    }
}

__global__ __launch_bounds__(256, 2) void attn_mma(const int* __restrict__ valid_lens, int S)
{
    extern __shared__ char smc[];
    const unsigned smb = (unsigned)__cvta_generic_to_shared(smc);

    const int tid = threadIdx.x, w = tid >> 5, lid = tid & 31;
    const int g = lid >> 2, t4 = lid & 3;
    const int lm = lid >> 3, lr = lid & 7;

    const int h = blockIdx.y, b = blockIdx.z;
    const int s0 = blockIdx.x * 128;
    const int valid = valid_lens[b];
    const long gbase = (long)b * S * DMODEL + h * 64;
    const __half* kg = g_kph + gbase;
    const __half* vg = g_vph + gbase;

    const int nt = (valid + 63) >> 6;

    // G0: Q tile [128 x 64]
#pragma unroll
    for (int i = 0; i < 4; ++i) {
        int f = tid + i * 256, r = f >> 3, c = f & 7;
        cp16(smb + (unsigned)(SMH_Q + r * PSTR + c * 8) * 2u,
             g_qph + gbase + (long)(s0 + r) * DMODEL + c * 8);
    }
    CP_COMMIT();
    // G1: tile0 -> slot0; G2: tile1 -> slot1 (maybe empty)
    issue_tile_h(smb + SMH_KV * 2u, kg, tid);
    issue_tile_h(smb + (SMH_KV + 64 * PSTR) * 2u, vg, tid);
    CP_COMMIT();
    if (nt > 1) {
        issue_tile_h(smb + (SMH_KV + SMH_SLOT) * 2u, kg + 64 * DMODEL, tid);
        issue_tile_h(smb + (SMH_KV + SMH_SLOT + 64 * PSTR) * 2u, vg + 64 * DMODEL, tid);
    }
    CP_COMMIT();

    CP_WAIT(2);            // Q ready
    __syncthreads();
    unsigned Qf[4][4];
#pragma unroll
    for (int kb = 0; kb < 4; ++kb) {
        unsigned addr = smb +
            ((SMH_Q + (w * 16 + (lm & 1) * 8 + lr) * PSTR + kb * 16 + (lm >> 1) * 8)) * 2u;
        ldmat4(Qf[kb][0], Qf[kb][1], Qf[kb][2], Qf[kb][3], addr);
    }

    float octx[8][4] = {};
    float lacc[4] = {};    // softmax denominators via P @ ones

    for (int t = 0; t < nt; ++t) {
        CP_WAIT(1);                      // tile t arrived (t+1 may be in flight)
        __syncthreads();                 // visible to all; slot (t-1)%3 free
        if (t + 2 < nt) {
            const int is = (t + 2) % 3;
            issue_tile_h(smb + (SMH_KV + is * SMH_SLOT) * 2u,
                         kg + (long)(t + 2) * 64 * DMODEL, tid);
            issue_tile_h(smb + (SMH_KV + is * SMH_SLOT + 64 * PSTR) * 2u,
                         vg + (long)(t + 2) * 64 * DMODEL, tid);
        }
        CP_COMMIT();

        const int slot = t % 3;
        const unsigned kbase = smb + (SMH_KV + slot * SMH_SLOT) * 2u;
        const unsigned vbase = kbase + (64 * PSTR) * 2u;
        const int j0 = t * 64;
        const bool masked = (t == nt - 1) && (valid & 63);

        // ---- S = Q @ K^T (scores arrive pre-multiplied by log2e) ----
        float sacc[8][4] = {};
#pragma unroll
        for (int kb = 0; kb < 4; ++kb)
#pragma unroll
            for (int np = 0; np < 4; ++np) {
                unsigned k0, k1, k2, k3;
                unsigned addr = kbase +
                    ((np * 16 + (lm & 1) * 8 + lr) * PSTR + kb * 16 + (lm >> 1) * 8) * 2u;
                ldmat4(k0, k1, k2, k3, addr);
                mma16(sacc[2 * np],     Qf[kb], k0, k2);
                mma16(sacc[2 * np + 1], Qf[kb], k1, k3);
            }

        // ---- P = 2^S via ex2.f16x2; pack directly into A-frags ----
        unsigned pa[4][4];
        if (!masked) {
#pragma unroll
            for (int nb = 0; nb < 8; ++nb) {
                pa[nb >> 1][2 * (nb & 1)]     = ex2h2(pkh2(sacc[nb][0], sacc[nb][1]));
                pa[nb >> 1][2 * (nb & 1) + 1] = ex2h2(pkh2(sacc[nb][2], sacc[nb][3]));
            }
        } else {
#pragma unroll
            for (int nb = 0; nb < 8; ++nb) {
                const int keya = j0 + nb * 8 + 2 * t4;
                const unsigned m = (keya < valid ? 0x00003C00u : 0u) |
                                   (keya + 1 < valid ? 0x3C000000u : 0u);
                pa[nb >> 1][2 * (nb & 1)]     = hmul2u(ex2h2(pkh2(sacc[nb][0], sacc[nb][1])), m);
                pa[nb >> 1][2 * (nb & 1) + 1] = hmul2u(ex2h2(pkh2(sacc[nb][2], sacc[nb][3])), m);
            }
        }

        // ---- l += P @ ones (row sums, fp32, accumulated across tiles) ----
#pragma unroll
        for (int kb = 0; kb < 4; ++kb)
            mma16(lacc, pa[kb], ONES2, ONES2);

        // ---- ctx += P @ V ----
#pragma unroll
        for (int kb = 0; kb < 4; ++kb)
#pragma unroll
            for (int np = 0; np < 4; ++np) {
                unsigned v0, v1, v2, v3;
                unsigned addr = vbase +
                    ((kb * 16 + (lm & 1) * 8 + lr) * PSTR + np * 16 + (lm >> 1) * 8) * 2u;
                ldmat4t(v0, v1, v2, v3, addr);
                mma16(octx[2 * np],     pa[kb], v0, v1);
                mma16(octx[2 * np + 1], pa[kb], v2, v3);
            }
    }

    // ---- epilogue: normalize (denominators already reduced by mma) ----
    const float inv0 = 1.0f / lacc[0];
    const float inv1 = 1.0f / lacc[2];
    __half* o0 = g_ctxh + gbase + (long)(s0 + w * 16 + g) * DMODEL;
    __half* o1 = o0 + 8 * DMODEL;
#pragma unroll
    for (int nb = 0; nb < 8; ++nb) {
        int c = nb * 8 + 2 * t4;
        *(unsigned*)(o0 + c) = pkh2(octx[nb][0] * inv0, octx[nb][1] * inv0);
        *(unsigned*)(o1 + c) = pkh2(octx[nb][2] * inv1, octx[nb][3] * inv1);
    }
}

// ---------------------------------------------------------------------------
// Kernel 3: output projection out = ctx @ Wo + bo (fp16 mma, fp32 out).
// Triple-buffered cp.async staging of ctx + Wo chunks; ONE barrier per chunk.
// smem: 3 slots x (A 128x72 + W 64x72) = 41472 halfs = 82944 B.
// ---------------------------------------------------------------------------
#define SMO_SLOT (128 * PSTR + 64 * PSTR)        // 13824 halfs
#define SMO_W    (128 * PSTR)                    // W pane offset within slot
#define SMO_TOTAL (3 * SMO_SLOT * 2)             // 82944 B
#define NCHUNK (DMODEL / 64)                     // 8

__device__ __forceinline__ void issue_chunk_o(unsigned slotb, const __half* actx,
                                              const __half* awo, int tid) {
    // A: 128 rows x 64 halfs
#pragma unroll
    for (int i = 0; i < 4; ++i) {
        int f = tid + i * 256, r = f >> 3, c = f & 7;
        cp16(slotb + (unsigned)(r * PSTR + c * 8) * 2u, actx + (long)r * DMODEL + c * 8);
    }
    // W: 64 rows x 64 halfs
#pragma unroll
    for (int i = 0; i < 2; ++i) {
        int f = tid + i * 256, r = f >> 3, c = f & 7;
        cp16(slotb + (unsigned)(SMO_W + r * PSTR + c * 8) * 2u, awo + (long)r * DMODEL + c * 8);
    }
}

__global__ __launch_bounds__(256, 2) void outp_tc(
    const float* __restrict__ bo, float* __restrict__ out)
{
    extern __shared__ char smc[];
    const unsigned smb = (unsigned)__cvta_generic_to_shared(smc);

    const int tid = threadIdx.x, w = tid >> 5, lid = tid & 31;
    const int g = lid >> 2, t4 = lid & 3;
    const int lm = lid >> 3, lr = lid & 7;
    const long r0 = (long)blockIdx.y * 128;
    const int n0 = blockIdx.x * 64;

    const __half* actx = g_ctxh + r0 * DMODEL;
    const __half* awo  = g_woh + n0;

    // prologue: chunks 0, 1
    issue_chunk_o(smb, actx, awo, tid);
    CP_COMMIT();
    issue_chunk_o(smb + SMO_SLOT * 2u, actx + 64, awo + 64 * DMODEL, tid);
    CP_COMMIT();

    float acc[8][4] = {};
    for (int t = 0; t < NCHUNK; ++t) {
        CP_WAIT(1);
        __syncthreads();
        if (t + 2 < NCHUNK) {
            const int is = (t + 2) % 3;
            issue_chunk_o(smb + (unsigned)(is * SMO_SLOT) * 2u,
                          actx + (t + 2) * 64, awo + (long)(t + 2) * 64 * DMODEL, tid);
        }
        CP_COMMIT();

        const unsigned abase = smb + (unsigned)((t % 3) * SMO_SLOT) * 2u;
        const unsigned wbase = abase + (unsigned)SMO_W * 2u;

#pragma unroll
        for (int kb = 0; kb < 4; ++kb) {
            unsigned af[4];
            unsigned aaddr = abase +
                ((16 * w + (lm & 1) * 8 + lr) * PSTR + kb * 16 + (lm >> 1) * 8) * 2u;
            ldmat4(af[0], af[1], af[2], af[3], aaddr);
#pragma unroll
            for (int np = 0; np < 4; ++np) {
                unsigned v0, v1, v2, v3;
                unsigned addr = wbase +
                    ((kb * 16 + (lm & 1) * 8 + lr) * PSTR + np * 16 + (lm >> 1) * 8) * 2u;
                ldmat4t(v0, v1, v2, v3, addr);
                mma16(acc[2 * np],     af, v0, v1);
                mma16(acc[2 * np + 1], af, v2, v3);
            }
        }
    }

    const long row0 = (r0 + 16 * w + g) * DMODEL + n0;
    const long row1 = row0 + 8 * DMODEL;
#pragma unroll
    for (int nb = 0; nb < 8; ++nb) {
        int c = nb * 8 + 2 * t4;
        float b0v = bo[n0 + c], b1v = bo[n0 + c + 1];
        *(float2*)(out + row0 + c) = make_float2(acc[nb][0] + b0v, acc[nb][1] + b1v);
        *(float2*)(out + row1 + c) = make_float2(acc[nb][2] + b0v, acc[nb][3] + b1v);
    }
}

// ---------------------------------------------------------------------------
// launch
// inputs: 0:q 1:k 2:v 3:Wq 4:bq 5:Wk 6:bk 7:Wv 8:bv 9:Wo 10:bo 11:valid_lens 12:max_len
// ---------------------------------------------------------------------------
extern "C" void kernel_launch(void* const* d_in, const int* in_sizes, int n_in,
                              void* d_out, int out_size)
{
    const float* q  = (const float*)d_in[0];
    const float* k  = (const float*)d_in[1];
    const float* v  = (const float*)d_in[2];
    const float* Wq = (const float*)d_in[3];
    const float* bq = (const float*)d_in[4];
    const float* Wk = (const float*)d_in[5];
    const float* bk = (const float*)d_in[6];
    const float* Wv = (const float*)d_in[7];
    const float* bv = (const float*)d_in[8];
    const float* Wo = (const float*)d_in[9];
    const float* bo = (const float*)d_in[10];
    const int* valid_lens = (const int*)d_in[11];
    float* out = (float*)d_out;

    const int B = in_sizes[11];
    const int S = in_sizes[0] / (B * DMODEL);
    const int BS = B * S;

    const int smGemm = (128 * PSTR + 64 * PSTR) * 2;   // 27648 B

    // 0) Wo -> fp16 (one-time per launch)
    cvt_wo<<<DMODEL * DMODEL / 1024, 256>>>(Wo);

    // 1) projections (x viewed as [BS*8, 64] rows)
    cudaFuncSetAttribute(proj_tc, cudaFuncAttributeMaxDynamicSharedMemorySize, smGemm);
    proj_tc<<<dim3(BS * 8 / 128, 3), 256, smGemm>>>(q, k, v, Wq, Wk, Wv, bq, bk, bv);

    // 2) fp16 flash attention (2 CTAs/SM, triple-buffered cp.async)
    cudaFuncSetAttribute(attn_mma, cudaFuncAttributeMaxDynamicSharedMemorySize, SMH_TOTAL);
    attn_mma<<<dim3(S / 128, NHEAD, B), 256, SMH_TOTAL>>>(valid_lens, S);

    // 3) output projection (triple-buffered cp.async)
    cudaFuncSetAttribute(outp_tc, cudaFuncAttributeMaxDynamicSharedMemorySize, SMO_TOTAL);
    outp_tc<<<dim3(DMODEL / 64, BS / 128), 256, SMO_TOTAL>>>(bo, out);
}